// round 1
// baseline (speedup 1.0000x reference)
#include <cuda_runtime.h>
#include <cuda_bf16.h>

// Problem constants
#define BB 8
#define NN_SEQ 2048
#define DD 1024

// Tiling
#define BM 128
#define BN 128
#define BK 16
#define PAD 4   // smem row stride = BM+PAD = 132 floats (16B aligned, kills STS conflicts)

// Scratch in __device__ globals (no cudaMalloc allowed)
__device__ float g_Q[(size_t)BB * NN_SEQ * DD];
__device__ float g_K[(size_t)BB * NN_SEQ * DD];
__device__ float g_V[(size_t)BB * NN_SEQ * DD];
__device__ float g_S[(size_t)BB * NN_SEQ * NN_SEQ];

// C[M,Nc] = A[M,K] * B  where B is [Nc,K] row-major if TRANSB (access B[n,k]),
// else [K,Nc] row-major (access B[k,n]). Batched via blockIdx.z with strides.
// If EPI: also write feat = C + text (same shape/stride as C, Nc == DD).
template<bool TRANSB, bool EPI>
__global__ void __launch_bounds__(256, 2)
gemm_kernel(const float* __restrict__ A, const float* __restrict__ Bm,
            float* __restrict__ C,
            int M, int Nc, int K,
            long sA, long sB, long sC,
            const float* __restrict__ text, float* __restrict__ feat, long sT)
{
    __shared__ float As[BK][BM + PAD];
    __shared__ float Bs[BK][BN + PAD];

    const int b = blockIdx.z;
    A  += (long)b * sA;
    Bm += (long)b * sB;
    C  += (long)b * sC;

    const int mBase = blockIdx.y * BM;
    const int nBase = blockIdx.x * BN;
    const int tid = threadIdx.x;          // 256 threads
    const int tx = tid & 15;              // 0..15
    const int ty = tid >> 4;              // 0..15

    float acc[8][8];
    #pragma unroll
    for (int i = 0; i < 8; ++i)
        #pragma unroll
        for (int j = 0; j < 8; ++j) acc[i][j] = 0.f;

    for (int k0 = 0; k0 < K; k0 += BK) {
        // ---- load A tile [BM x BK], store transposed As[k][m] ----
        {
            int r = tid >> 2;             // 0..63, then +64
            const int c = (tid & 3) * 4;  // 0,4,8,12
            #pragma unroll
            for (int it = 0; it < 2; ++it, r += 64) {
                float4 v = *(const float4*)&A[(long)(mBase + r) * K + k0 + c];
                As[c + 0][r] = v.x;
                As[c + 1][r] = v.y;
                As[c + 2][r] = v.z;
                As[c + 3][r] = v.w;
            }
        }
        // ---- load B tile into Bs[k][n] ----
        if (TRANSB) {
            int r = tid >> 2;
            const int c = (tid & 3) * 4;
            #pragma unroll
            for (int it = 0; it < 2; ++it, r += 64) {
                float4 v = *(const float4*)&Bm[(long)(nBase + r) * K + k0 + c];
                Bs[c + 0][r] = v.x;
                Bs[c + 1][r] = v.y;
                Bs[c + 2][r] = v.z;
                Bs[c + 3][r] = v.w;
            }
        } else {
            int r = tid >> 5;             // 0..7, then +8
            const int c = (tid & 31) * 4; // 0..124
            #pragma unroll
            for (int it = 0; it < 2; ++it, r += 8) {
                float4 v = *(const float4*)&Bm[(long)(k0 + r) * Nc + nBase + c];
                *(float4*)&Bs[r][c] = v;
            }
        }
        __syncthreads();

        // ---- 8x8 register tile FMA ----
        #pragma unroll
        for (int k = 0; k < BK; ++k) {
            float a[8], bv[8];
            *(float4*)&a[0]  = *(const float4*)&As[k][ty * 8];
            *(float4*)&a[4]  = *(const float4*)&As[k][ty * 8 + 4];
            *(float4*)&bv[0] = *(const float4*)&Bs[k][tx * 8];
            *(float4*)&bv[4] = *(const float4*)&Bs[k][tx * 8 + 4];
            #pragma unroll
            for (int i = 0; i < 8; ++i)
                #pragma unroll
                for (int j = 0; j < 8; ++j)
                    acc[i][j] += a[i] * bv[j];
        }
        __syncthreads();
    }

    // ---- epilogue ----
    #pragma unroll
    for (int i = 0; i < 8; ++i) {
        const int row = mBase + ty * 8 + i;
        #pragma unroll
        for (int j = 0; j < 8; j += 4) {
            const int col = nBase + tx * 8 + j;
            float4 v;
            v.x = acc[i][j + 0];
            v.y = acc[i][j + 1];
            v.z = acc[i][j + 2];
            v.w = acc[i][j + 3];
            *(float4*)&C[(long)row * Nc + col] = v;
            if (EPI) {
                const long idx = (long)b * sT + (long)row * Nc + col;
                float4 t = *(const float4*)&text[idx];
                float4 f;
                f.x = v.x + t.x; f.y = v.y + t.y; f.z = v.z + t.z; f.w = v.w + t.w;
                *(float4*)&feat[idx] = f;
            }
        }
    }
}

// Softmax over the QUERY axis (n) of S[b][n][m]: each thread owns one column m.
// Online max+sumexp in pass 1, normalize-write in pass 2. Coalesced (threads span m).
__global__ void softmax_cols_kernel(float* __restrict__ S, int N, int M)
{
    const int b = blockIdx.y;
    const int m = blockIdx.x * blockDim.x + threadIdx.x;
    float* Sb = S + (long)b * N * M;

    float mx = -3.4e38f;
    float s = 0.f;
    for (int n = 0; n < N; ++n) {
        float x = Sb[(long)n * M + m];
        float nm = fmaxf(mx, x);
        s = s * __expf(mx - nm) + __expf(x - nm);
        mx = nm;
    }
    const float inv = 1.f / s;
    for (int n = 0; n < N; ++n) {
        float x = Sb[(long)n * M + m];
        Sb[(long)n * M + m] = __expf(x - mx) * inv;
    }
}

extern "C" void kernel_launch(void* const* d_in, const int* in_sizes, int n_in,
                              void* d_out, int out_size)
{
    const float* img  = (const float*)d_in[0];
    const float* text = (const float*)d_in[1];
    const float* Wq   = (const float*)d_in[2];
    const float* Wk   = (const float*)d_in[3];
    const float* Wv   = (const float*)d_in[4];

    float* out  = (float*)d_out;
    float* feat = out + (size_t)BB * NN_SEQ * DD;

    float *Q, *K, *V, *S;
    cudaGetSymbolAddress((void**)&Q, g_Q);
    cudaGetSymbolAddress((void**)&K, g_K);
    cudaGetSymbolAddress((void**)&V, g_V);
    cudaGetSymbolAddress((void**)&S, g_S);

    const long nd = (long)NN_SEQ * DD;       // per-batch Q/K/V/out stride
    const long nn = (long)NN_SEQ * NN_SEQ;   // per-batch S stride
    const int  MT = BB * NN_SEQ;             // 16384 flattened rows for projections

    dim3 blk(256);

    // Projections: [16384,1024] = X[16384,1024] * W[1024,1024]^T  (NT)
    dim3 gproj(DD / BN, MT / BM, 1);
    gemm_kernel<true, false><<<gproj, blk>>>(img,  Wq, Q, MT, DD, DD, 0, 0, 0, nullptr, nullptr, 0);
    gemm_kernel<true, false><<<gproj, blk>>>(text, Wk, K, MT, DD, DD, 0, 0, 0, nullptr, nullptr, 0);
    gemm_kernel<true, false><<<gproj, blk>>>(text, Wv, V, MT, DD, DD, 0, 0, 0, nullptr, nullptr, 0);

    // Scores: per batch S[2048,2048] = Q[2048,1024] * K[2048,1024]^T  (NT)
    dim3 gsc(NN_SEQ / BN, NN_SEQ / BM, BB);
    gemm_kernel<true, false><<<gsc, blk>>>(Q, K, S, NN_SEQ, NN_SEQ, DD, nd, nd, nn, nullptr, nullptr, 0);

    // Softmax over query axis (columns of each S_b in this layout)
    dim3 gsm(NN_SEQ / 256, BB);
    softmax_cols_kernel<<<gsm, blk>>>(S, NN_SEQ, NN_SEQ);

    // Output: per batch out[2048,1024] = alpha[2048,2048] * V[2048,1024]  (NN)
    // Epilogue writes out and feature = out + text.
    dim3 gout(DD / BN, NN_SEQ / BM, BB);
    gemm_kernel<false, true><<<gout, blk>>>(S, V, out, NN_SEQ, DD, NN_SEQ, nn, nd, nd, text, feat, nd);
}

// round 5
// speedup vs baseline: 2.3759x; 2.3759x over previous
#include <cuda_runtime.h>
#include <cuda_bf16.h>
#include <cstdint>

// ---------------- problem constants ----------------
#define BB   8
#define SEQ  2048
#define DIM  1024
#define MT   (BB * SEQ)          // 16384 flattened rows for projections

// ---------------- small PTX helpers (all base-target legal: sm_80+) ----------------
__device__ __forceinline__ uint32_t smem_to_u32(const void* p) {
    uint32_t a;
    asm("{ .reg .u64 t; cvta.to.shared.u64 t, %1; cvt.u32.u64 %0, t; }" : "=r"(a) : "l"(p));
    return a;
}
#define CP_ASYNC16(dst, src) \
    asm volatile("cp.async.cg.shared.global [%0], [%1], 16;" :: "r"(dst), "l"(src))
#define CP_COMMIT() asm volatile("cp.async.commit_group;" ::: "memory")
#define CP_WAIT1()  asm volatile("cp.async.wait_group 1;" ::: "memory")
#define CP_WAIT0()  asm volatile("cp.async.wait_group 0;" ::: "memory")

__device__ __forceinline__ void ldsm_x4(uint32_t* r, uint32_t addr) {
    asm volatile("ldmatrix.sync.aligned.m8n8.x4.shared.b16 {%0,%1,%2,%3}, [%4];"
                 : "=r"(r[0]), "=r"(r[1]), "=r"(r[2]), "=r"(r[3]) : "r"(addr));
}
__device__ __forceinline__ void mma16816(float* c, const uint32_t* a, const uint32_t* b) {
    asm volatile(
        "mma.sync.aligned.m16n8k16.row.col.f32.bf16.bf16.f32 "
        "{%0,%1,%2,%3}, {%4,%5,%6,%7}, {%8,%9}, {%0,%1,%2,%3};"
        : "+f"(c[0]), "+f"(c[1]), "+f"(c[2]), "+f"(c[3])
        : "r"(a[0]), "r"(a[1]), "r"(a[2]), "r"(a[3]), "r"(b[0]), "r"(b[1]));
}

// ---------------- scratch (no cudaMalloc allowed) ----------------
__device__ __nv_bfloat16 g_img_h[(size_t)MT * DIM], g_img_l[(size_t)MT * DIM];
__device__ __nv_bfloat16 g_text_h[(size_t)MT * DIM], g_text_l[(size_t)MT * DIM];
__device__ __nv_bfloat16 g_Wq_h[(size_t)DIM * DIM], g_Wq_l[(size_t)DIM * DIM];
__device__ __nv_bfloat16 g_Wk_h[(size_t)DIM * DIM], g_Wk_l[(size_t)DIM * DIM];
__device__ __nv_bfloat16 g_Wv_h[(size_t)DIM * DIM], g_Wv_l[(size_t)DIM * DIM];
__device__ __nv_bfloat16 g_Qh[(size_t)MT * DIM], g_Ql[(size_t)MT * DIM];
__device__ __nv_bfloat16 g_Kh[(size_t)MT * DIM], g_Kl[(size_t)MT * DIM];
__device__ float         g_V[(size_t)MT * DIM];
__device__ __nv_bfloat16 g_Vth[(size_t)MT * DIM], g_Vtl[(size_t)MT * DIM];   // [B][DIM][SEQ]
__device__ float         g_S[(size_t)BB * SEQ * SEQ];
__device__ __nv_bfloat16 g_Ah[(size_t)BB * SEQ * SEQ], g_Al[(size_t)BB * SEQ * SEQ];

// ---------------- GEMM: C[M,Nc] ~= (Ah+Al) @ (Bh+Bl)^T via 3 bf16 HMMA terms ----------------
// BM=128, BN=128, BK=32, 2-stage cp.async pipeline.
// SMEM rows padded to 80B (32 bf16 data + 8 pad) -> conflict-free ldmatrix & cp.async.
#define ROWB   80
#define TILEB  (128 * ROWB)      // 10240
#define T_AH   0
#define T_AL   TILEB
#define T_BH   (2 * TILEB)
#define T_BL   (3 * TILEB)
#define STAGE  (4 * TILEB)       // 40960
#define SMEM_TOTAL (2 * STAGE)   // 81920

template<int EPI>   // 0: fp32 C   1: split bf16 Ch/Cl   2: fp32 C + feat=C+text
__global__ void __launch_bounds__(256, 1)
gemm_hmma3(const __nv_bfloat16* __restrict__ Ah, const __nv_bfloat16* __restrict__ Al,
           const __nv_bfloat16* __restrict__ Bh, const __nv_bfloat16* __restrict__ Bl,
           int M, int Nc, int Kd, long sA, long sB, long sC,
           float* __restrict__ C, __nv_bfloat16* __restrict__ Ch, __nv_bfloat16* __restrict__ Cl,
           const float* __restrict__ text, float* __restrict__ feat, long sT)
{
    extern __shared__ char smem[];
    const uint32_t sbase = smem_to_u32(smem);
    const int tid = threadIdx.x;
    const int wid = tid >> 5;
    const int lid = tid & 31;
    const int b = blockIdx.z;

    Ah += (long)b * sA;  Al += (long)b * sA;
    Bh += (long)b * sB;  Bl += (long)b * sB;

    const int mBase = blockIdx.y * 128;
    const int nBase = blockIdx.x * 128;

    // per-thread cp.async source rows/cols (4 tiles x 2 chunks of 16B)
    const int ch_r0 = tid >> 2;                 // chunk row for chunk index tid
    const int ch_c0 = (tid & 3) * 16;           // byte col
    const int ch_r1 = (tid + 256) >> 2;
    const int ch_c1 = ((tid + 256) & 3) * 16;

    const __nv_bfloat16* gT[4] = { Ah + (long)mBase * Kd, Al + (long)mBase * Kd,
                                   Bh + (long)nBase * Kd, Bl + (long)nBase * Kd };

    auto load_stage = [&](int k0, int s) {
        const uint32_t st = sbase + s * STAGE;
        #pragma unroll
        for (int tile = 0; tile < 4; ++tile) {
            const char* g0 = (const char*)(gT[tile] + (long)ch_r0 * Kd + k0) + ch_c0;
            const char* g1 = (const char*)(gT[tile] + (long)ch_r1 * Kd + k0) + ch_c1;
            CP_ASYNC16(st + tile * TILEB + ch_r0 * ROWB + ch_c0, g0);
            CP_ASYNC16(st + tile * TILEB + ch_r1 * ROWB + ch_c1, g1);
        }
    };

    // warp tile: 64 (m) x 32 (n)
    const int wm = (wid >> 2) * 64;
    const int wn = (wid & 3) * 32;

    // ldmatrix per-lane address components
    const uint32_t aOff = (uint32_t)((lid & 15) * ROWB + (lid >> 4) * 16);
    const uint32_t bOff = (uint32_t)((((lid >> 4) << 3) + (lid & 7)) * ROWB + ((lid >> 3) & 1) * 16);

    float acc[4][4][4];
    #pragma unroll
    for (int mi = 0; mi < 4; ++mi)
        #pragma unroll
        for (int ni = 0; ni < 4; ++ni)
            #pragma unroll
            for (int q = 0; q < 4; ++q) acc[mi][ni][q] = 0.f;

    const int nch = Kd >> 5;

    load_stage(0, 0); CP_COMMIT();

    for (int i = 0; i < nch; ++i) {
        if (i + 1 < nch) { load_stage((i + 1) << 5, (i + 1) & 1); CP_COMMIT(); CP_WAIT1(); }
        else            { CP_WAIT0(); }
        __syncthreads();

        const uint32_t st = sbase + (i & 1) * STAGE;
        const uint32_t aBase = st + (uint32_t)(wm * ROWB);
        const uint32_t bBase = st + (uint32_t)(wn * ROWB);

        #pragma unroll
        for (int kk = 0; kk < 2; ++kk) {
            const uint32_t kb = kk * 32;   // 16 bf16 = 32 bytes
            uint32_t ah[4][4], alr[4][4], bh8[8], bl8[8];
            #pragma unroll
            for (int mi = 0; mi < 4; ++mi) {
                ldsm_x4(ah[mi],  aBase + T_AH + (uint32_t)(mi * 16 * ROWB) + aOff + kb);
                ldsm_x4(alr[mi], aBase + T_AL + (uint32_t)(mi * 16 * ROWB) + aOff + kb);
            }
            #pragma unroll
            for (int nb = 0; nb < 2; ++nb) {
                ldsm_x4(&bh8[nb * 4], bBase + T_BH + (uint32_t)(nb * 16 * ROWB) + bOff + kb);
                ldsm_x4(&bl8[nb * 4], bBase + T_BL + (uint32_t)(nb * 16 * ROWB) + bOff + kb);
            }
            #pragma unroll
            for (int mi = 0; mi < 4; ++mi)
                #pragma unroll
                for (int ni = 0; ni < 4; ++ni) {
                    mma16816(acc[mi][ni], ah[mi],  &bh8[ni * 2]);
                    mma16816(acc[mi][ni], ah[mi],  &bl8[ni * 2]);
                    mma16816(acc[mi][ni], alr[mi], &bh8[ni * 2]);
                }
        }
        __syncthreads();
    }

    // ---- epilogue ----
    const int rowA = mBase + wm + (lid >> 2);
    const int colA = nBase + wn + (lid & 3) * 2;
    #pragma unroll
    for (int mi = 0; mi < 4; ++mi) {
        #pragma unroll
        for (int half = 0; half < 2; ++half) {
            const int row = rowA + mi * 16 + half * 8;
            #pragma unroll
            for (int ni = 0; ni < 4; ++ni) {
                const int col = colA + ni * 8;
                const float v0 = acc[mi][ni][half * 2 + 0];
                const float v1 = acc[mi][ni][half * 2 + 1];
                if (EPI == 0) {
                    float2 v; v.x = v0; v.y = v1;
                    *(float2*)(C + (long)b * sC + (long)row * Nc + col) = v;
                } else if (EPI == 1) {
                    const __nv_bfloat16 h0 = __float2bfloat16_rn(v0);
                    const __nv_bfloat16 h1 = __float2bfloat16_rn(v1);
                    __nv_bfloat162 ph, pl;
                    ph.x = h0; ph.y = h1;
                    pl.x = __float2bfloat16_rn(v0 - __bfloat162float(h0));
                    pl.y = __float2bfloat16_rn(v1 - __bfloat162float(h1));
                    *(__nv_bfloat162*)(Ch + (long)b * sC + (long)row * Nc + col) = ph;
                    *(__nv_bfloat162*)(Cl + (long)b * sC + (long)row * Nc + col) = pl;
                } else {
                    float2 v; v.x = v0; v.y = v1;
                    *(float2*)(C + (long)b * sC + (long)row * Nc + col) = v;
                    const float2 t = *(const float2*)(text + (long)b * sT + (long)row * Nc + col);
                    float2 f; f.x = v.x + t.x; f.y = v.y + t.y;
                    *(float2*)(feat + (long)b * sT + (long)row * Nc + col) = f;
                }
            }
        }
    }
}

// ---------------- fp32 -> bf16 hi/lo split ----------------
__global__ void split_kernel(const float* __restrict__ s, __nv_bfloat16* __restrict__ h,
                             __nv_bfloat16* __restrict__ l, int n4)
{
    const int i = blockIdx.x * blockDim.x + threadIdx.x;
    if (i >= n4) return;
    const float4 v = ((const float4*)s)[i];
    __nv_bfloat16 h0 = __float2bfloat16_rn(v.x), h1 = __float2bfloat16_rn(v.y);
    __nv_bfloat16 h2 = __float2bfloat16_rn(v.z), h3 = __float2bfloat16_rn(v.w);
    union { uint2 u; __nv_bfloat16 q[4]; } ph, pl;
    ph.q[0] = h0; ph.q[1] = h1; ph.q[2] = h2; ph.q[3] = h3;
    pl.q[0] = __float2bfloat16_rn(v.x - __bfloat162float(h0));
    pl.q[1] = __float2bfloat16_rn(v.y - __bfloat162float(h1));
    pl.q[2] = __float2bfloat16_rn(v.z - __bfloat162float(h2));
    pl.q[3] = __float2bfloat16_rn(v.w - __bfloat162float(h3));
    ((uint2*)h)[i] = ph.u;
    ((uint2*)l)[i] = pl.u;
}

// ---------------- V transpose + split: V[b][n][d] -> Vt[b][d][n] ----------------
__global__ void vtrans_kernel(const float* __restrict__ V,
                              __nv_bfloat16* __restrict__ Th, __nv_bfloat16* __restrict__ Tl)
{
    __shared__ float t[32][33];
    const int b = blockIdx.z;
    const float* Vb = V + (size_t)b * SEQ * DIM;
    const int n0 = blockIdx.x * 32, d0 = blockIdx.y * 32;
    #pragma unroll
    for (int r = threadIdx.y; r < 32; r += 8)
        t[r][threadIdx.x] = Vb[(size_t)(n0 + r) * DIM + d0 + threadIdx.x];
    __syncthreads();
    __nv_bfloat16* Thb = Th + (size_t)b * DIM * SEQ;
    __nv_bfloat16* Tlb = Tl + (size_t)b * DIM * SEQ;
    #pragma unroll
    for (int r = threadIdx.y; r < 32; r += 8) {
        const float v = t[threadIdx.x][r];
        const __nv_bfloat16 h = __float2bfloat16_rn(v);
        Thb[(size_t)(d0 + r) * SEQ + n0 + threadIdx.x] = h;
        Tlb[(size_t)(d0 + r) * SEQ + n0 + threadIdx.x] = __float2bfloat16_rn(v - __bfloat162float(h));
    }
}

// ---------------- softmax over QUERY axis (n of S[b][n][m]); writes split bf16 alpha ----------------
__global__ void softmax_cols_kernel(const float* __restrict__ S,
                                    __nv_bfloat16* __restrict__ Ah, __nv_bfloat16* __restrict__ Al)
{
    const int b = blockIdx.y;
    const int m = blockIdx.x * blockDim.x + threadIdx.x;
    const float* Sb = S + (size_t)b * SEQ * SEQ;
    __nv_bfloat16* Ahb = Ah + (size_t)b * SEQ * SEQ;
    __nv_bfloat16* Alb = Al + (size_t)b * SEQ * SEQ;

    float mx = -3.4e38f, s = 0.f;
    for (int n = 0; n < SEQ; ++n) {
        const float x = Sb[(size_t)n * SEQ + m];
        const float nm = fmaxf(mx, x);
        s = s * __expf(mx - nm) + __expf(x - nm);
        mx = nm;
    }
    const float inv = 1.f / s;
    for (int n = 0; n < SEQ; ++n) {
        const float x = Sb[(size_t)n * SEQ + m];
        const float a = __expf(x - mx) * inv;
        const __nv_bfloat16 h = __float2bfloat16_rn(a);
        Ahb[(size_t)n * SEQ + m] = h;
        Alb[(size_t)n * SEQ + m] = __float2bfloat16_rn(a - __bfloat162float(h));
    }
}

// ---------------- launch ----------------
extern "C" void kernel_launch(void* const* d_in, const int* in_sizes, int n_in,
                              void* d_out, int out_size)
{
    const float* img  = (const float*)d_in[0];
    const float* text = (const float*)d_in[1];
    const float* Wq   = (const float*)d_in[2];
    const float* Wk   = (const float*)d_in[3];
    const float* Wv   = (const float*)d_in[4];

    float* out  = (float*)d_out;
    float* feat = out + (size_t)MT * DIM;

    __nv_bfloat16 *imgh, *imgl, *texth, *textl, *wqh, *wql, *wkh, *wkl, *wvh, *wvl;
    __nv_bfloat16 *qh, *ql, *kh, *kl, *vth, *vtl, *ah, *al;
    float *v, *s;
    cudaGetSymbolAddress((void**)&imgh, g_img_h);  cudaGetSymbolAddress((void**)&imgl, g_img_l);
    cudaGetSymbolAddress((void**)&texth, g_text_h); cudaGetSymbolAddress((void**)&textl, g_text_l);
    cudaGetSymbolAddress((void**)&wqh, g_Wq_h);    cudaGetSymbolAddress((void**)&wql, g_Wq_l);
    cudaGetSymbolAddress((void**)&wkh, g_Wk_h);    cudaGetSymbolAddress((void**)&wkl, g_Wk_l);
    cudaGetSymbolAddress((void**)&wvh, g_Wv_h);    cudaGetSymbolAddress((void**)&wvl, g_Wv_l);
    cudaGetSymbolAddress((void**)&qh, g_Qh);       cudaGetSymbolAddress((void**)&ql, g_Ql);
    cudaGetSymbolAddress((void**)&kh, g_Kh);       cudaGetSymbolAddress((void**)&kl, g_Kl);
    cudaGetSymbolAddress((void**)&v, g_V);
    cudaGetSymbolAddress((void**)&vth, g_Vth);     cudaGetSymbolAddress((void**)&vtl, g_Vtl);
    cudaGetSymbolAddress((void**)&s, g_S);
    cudaGetSymbolAddress((void**)&ah, g_Ah);       cudaGetSymbolAddress((void**)&al, g_Al);

    cudaFuncSetAttribute(gemm_hmma3<0>, cudaFuncAttributeMaxDynamicSharedMemorySize, SMEM_TOTAL);
    cudaFuncSetAttribute(gemm_hmma3<1>, cudaFuncAttributeMaxDynamicSharedMemorySize, SMEM_TOTAL);
    cudaFuncSetAttribute(gemm_hmma3<2>, cudaFuncAttributeMaxDynamicSharedMemorySize, SMEM_TOTAL);

    const long nd = (long)SEQ * DIM;    // 2 M
    const long nn = (long)SEQ * SEQ;    // 4 M

    // 1. split inputs
    {
        const int n4i = MT * DIM / 4;
        split_kernel<<<n4i / 256, 256>>>(img,  imgh,  imgl,  n4i);
        split_kernel<<<n4i / 256, 256>>>(text, texth, textl, n4i);
        const int n4w = DIM * DIM / 4;
        split_kernel<<<n4w / 256, 256>>>(Wq, wqh, wql, n4w);
        split_kernel<<<n4w / 256, 256>>>(Wk, wkh, wkl, n4w);
        split_kernel<<<n4w / 256, 256>>>(Wv, wvh, wvl, n4w);
    }

    // 2. projections: [16384,1024] = X @ W^T
    {
        dim3 g(DIM / 128, MT / 128, 1), blk(256);
        gemm_hmma3<1><<<g, blk, SMEM_TOTAL>>>(imgh, imgl, wqh, wql, MT, DIM, DIM, 0, 0, 0,
                                              nullptr, qh, ql, nullptr, nullptr, 0);
        gemm_hmma3<1><<<g, blk, SMEM_TOTAL>>>(texth, textl, wkh, wkl, MT, DIM, DIM, 0, 0, 0,
                                              nullptr, kh, kl, nullptr, nullptr, 0);
        gemm_hmma3<0><<<g, blk, SMEM_TOTAL>>>(texth, textl, wvh, wvl, MT, DIM, DIM, 0, 0, 0,
                                              v, nullptr, nullptr, nullptr, nullptr, 0);
    }

    // 3. transpose + split V
    {
        dim3 g(SEQ / 32, DIM / 32, BB), blk(32, 8);
        vtrans_kernel<<<g, blk>>>(v, vth, vtl);
    }

    // 4. scores: per batch S[2048,2048] = Q @ K^T
    {
        dim3 g(SEQ / 128, SEQ / 128, BB), blk(256);
        gemm_hmma3<0><<<g, blk, SMEM_TOTAL>>>(qh, ql, kh, kl, SEQ, SEQ, DIM, nd, nd, nn,
                                              s, nullptr, nullptr, nullptr, nullptr, 0);
    }

    // 5. softmax over query axis, write split bf16 alpha
    {
        dim3 g(SEQ / 256, BB), blk(256);
        softmax_cols_kernel<<<g, blk>>>(s, ah, al);
    }

    // 6. out = alpha @ V ;  feature = out + text
    {
        dim3 g(DIM / 128, SEQ / 128, BB), blk(256);
        gemm_hmma3<2><<<g, blk, SMEM_TOTAL>>>(ah, al, vth, vtl, SEQ, DIM, SEQ, nn, nd, nd,
                                              out, nullptr, nullptr, text, feat, nd);
    }
}

// round 6
// speedup vs baseline: 2.3951x; 1.0081x over previous
#include <cuda_runtime.h>
#include <cuda_bf16.h>
#include <cstdint>

// ---------------- problem constants ----------------
#define BB   8
#define SEQ  2048
#define DIM  1024
#define MT   (BB * SEQ)          // 16384 flattened rows for projections

// ---------------- PTX helpers (base-target legal, sm_80+) ----------------
__device__ __forceinline__ uint32_t smem_to_u32(const void* p) {
    uint32_t a;
    asm("{ .reg .u64 t; cvta.to.shared.u64 t, %1; cvt.u32.u64 %0, t; }" : "=r"(a) : "l"(p));
    return a;
}
#define CP_ASYNC16(dst, src) \
    asm volatile("cp.async.cg.shared.global [%0], [%1], 16;" :: "r"(dst), "l"(src))
#define CP_COMMIT() asm volatile("cp.async.commit_group;" ::: "memory")
#define CP_WAIT2()  asm volatile("cp.async.wait_group 2;" ::: "memory")
#define CP_WAIT1()  asm volatile("cp.async.wait_group 1;" ::: "memory")
#define CP_WAIT0()  asm volatile("cp.async.wait_group 0;" ::: "memory")

__device__ __forceinline__ void ldsm_x4(uint32_t* r, uint32_t addr) {
    asm volatile("ldmatrix.sync.aligned.m8n8.x4.shared.b16 {%0,%1,%2,%3}, [%4];"
                 : "=r"(r[0]), "=r"(r[1]), "=r"(r[2]), "=r"(r[3]) : "r"(addr));
}
__device__ __forceinline__ void mma16816(float* c, const uint32_t* a, const uint32_t* b) {
    asm volatile(
        "mma.sync.aligned.m16n8k16.row.col.f32.bf16.bf16.f32 "
        "{%0,%1,%2,%3}, {%4,%5,%6,%7}, {%8,%9}, {%0,%1,%2,%3};"
        : "+f"(c[0]), "+f"(c[1]), "+f"(c[2]), "+f"(c[3])
        : "r"(a[0]), "r"(a[1]), "r"(a[2]), "r"(a[3]), "r"(b[0]), "r"(b[1]));
}

// ---------------- scratch (no cudaMalloc allowed) ----------------
__device__ __nv_bfloat16 g_img_h[(size_t)MT * DIM], g_img_l[(size_t)MT * DIM];
__device__ __nv_bfloat16 g_text_h[(size_t)MT * DIM], g_text_l[(size_t)MT * DIM];
__device__ __nv_bfloat16 g_Wq_h[(size_t)DIM * DIM], g_Wq_l[(size_t)DIM * DIM];
__device__ __nv_bfloat16 g_Wk_h[(size_t)DIM * DIM], g_Wk_l[(size_t)DIM * DIM];
__device__ __nv_bfloat16 g_Wv_h[(size_t)DIM * DIM], g_Wv_l[(size_t)DIM * DIM];
__device__ __nv_bfloat16 g_Qh[(size_t)MT * DIM], g_Ql[(size_t)MT * DIM];
__device__ __nv_bfloat16 g_Kh[(size_t)MT * DIM], g_Kl[(size_t)MT * DIM];
__device__ float         g_V[(size_t)MT * DIM];
__device__ __nv_bfloat16 g_Vth[(size_t)MT * DIM], g_Vtl[(size_t)MT * DIM];   // [B][DIM][SEQ]
__device__ float         g_S[(size_t)BB * SEQ * SEQ];
__device__ __nv_bfloat16 g_Ah[(size_t)BB * SEQ * SEQ], g_Al[(size_t)BB * SEQ * SEQ];

// ---------------- GEMM: C[M,Nc] ~= (Ah+Al) @ (Bh+Bl)^T via 3 bf16 HMMA terms ----------------
// BM=128, BN=256, BK=32, 3-stage cp.async pipeline, warp tile 64x64 (8 warps, 2x4).
// SMEM rows padded to 80B (32 bf16 + 8 pad) -> conflict-free ldmatrix & cp.async.
#define ROWB     80
#define TILEB_A  (128 * ROWB)            // 10240
#define TILEB_B  (256 * ROWB)            // 20480
#define T_AH     0
#define T_AL     TILEB_A
#define T_BH     (2 * TILEB_A)
#define T_BL     (2 * TILEB_A + TILEB_B)
#define STAGE    (2 * TILEB_A + 2 * TILEB_B)   // 61440
#define SMEM_TOTAL (3 * STAGE)                  // 184320

template<int EPI>   // 0: fp32 C   1: split bf16 Ch/Cl   2: fp32 C + feat=C+text
__global__ void __launch_bounds__(256, 1)
gemm_hmma3(const __nv_bfloat16* __restrict__ Ah, const __nv_bfloat16* __restrict__ Al,
           const __nv_bfloat16* __restrict__ Bh, const __nv_bfloat16* __restrict__ Bl,
           int M, int Nc, int Kd, long sA, long sB, long sC,
           float* __restrict__ C, __nv_bfloat16* __restrict__ Ch, __nv_bfloat16* __restrict__ Cl,
           const float* __restrict__ text, float* __restrict__ feat, long sT)
{
    extern __shared__ char smem[];
    const uint32_t sbase = smem_to_u32(smem);
    const int tid = threadIdx.x;
    const int wid = tid >> 5;
    const int lid = tid & 31;
    const int b = blockIdx.z;

    const int mBase = blockIdx.y * 128;
    const int nBase = blockIdx.x * 256;

    const __nv_bfloat16* gAh = Ah + (long)b * sA + (long)mBase * Kd;
    const __nv_bfloat16* gAl = Al + (long)b * sA + (long)mBase * Kd;
    const __nv_bfloat16* gBh = Bh + (long)b * sB + (long)nBase * Kd;
    const __nv_bfloat16* gBl = Bl + (long)b * sB + (long)nBase * Kd;

    auto load_stage = [&](int k0, int s) {
        const uint32_t st = sbase + (uint32_t)s * STAGE;
        // A tiles: 512 16B chunks each -> 2 per thread
        #pragma unroll
        for (int c = 0; c < 2; ++c) {
            const int ch = tid + c * 256;
            const int r = ch >> 2, col = (ch & 3) * 16;
            CP_ASYNC16(st + T_AH + r * ROWB + col, (const char*)(gAh + (long)r * Kd + k0) + col);
            CP_ASYNC16(st + T_AL + r * ROWB + col, (const char*)(gAl + (long)r * Kd + k0) + col);
        }
        // B tiles: 1024 chunks each -> 4 per thread
        #pragma unroll
        for (int c = 0; c < 4; ++c) {
            const int ch = tid + c * 256;
            const int r = ch >> 2, col = (ch & 3) * 16;
            CP_ASYNC16(st + T_BH + r * ROWB + col, (const char*)(gBh + (long)r * Kd + k0) + col);
            CP_ASYNC16(st + T_BL + r * ROWB + col, (const char*)(gBl + (long)r * Kd + k0) + col);
        }
    };

    // warp tile: 64 (m) x 64 (n); warp grid 2 (m) x 4 (n)
    const int wm = (wid >> 2) * 64;
    const int wn = (wid & 3) * 64;

    const uint32_t aOff = (uint32_t)((lid & 15) * ROWB + (lid >> 4) * 16);
    const uint32_t bOff = (uint32_t)((((lid >> 4) << 3) + (lid & 7)) * ROWB + ((lid >> 3) & 1) * 16);

    float acc[4][8][4];
    #pragma unroll
    for (int mi = 0; mi < 4; ++mi)
        #pragma unroll
        for (int ni = 0; ni < 8; ++ni)
            #pragma unroll
            for (int q = 0; q < 4; ++q) acc[mi][ni][q] = 0.f;

    const int nch = Kd >> 5;

    load_stage(0, 0);  CP_COMMIT();
    load_stage(32, 1); CP_COMMIT();

    int cur = 0, nxt = 2;
    for (int i = 0; i < nch; ++i) {
        if (i + 2 < nch) {
            load_stage((i + 2) << 5, nxt); CP_COMMIT(); CP_WAIT2();
        } else if (i + 1 < nch) {
            CP_WAIT1();
        } else {
            CP_WAIT0();
        }
        __syncthreads();

        const uint32_t st = sbase + (uint32_t)cur * STAGE;
        const uint32_t aBase = st + (uint32_t)(wm * ROWB);
        const uint32_t bBase = st + (uint32_t)(wn * ROWB);

        #pragma unroll
        for (int kk = 0; kk < 2; ++kk) {
            const uint32_t kb = kk * 32;   // 16 bf16 = 32 bytes
            uint32_t ah[4][4], al4[4][4];
            #pragma unroll
            for (int mi = 0; mi < 4; ++mi) {
                ldsm_x4(ah[mi],  aBase + T_AH + (uint32_t)(mi * 16 * ROWB) + aOff + kb);
                ldsm_x4(al4[mi], aBase + T_AL + (uint32_t)(mi * 16 * ROWB) + aOff + kb);
            }
            #pragma unroll
            for (int nh = 0; nh < 2; ++nh) {
                uint32_t bh8[8], bl8[8];
                #pragma unroll
                for (int nb = 0; nb < 2; ++nb) {
                    const uint32_t nrow = (uint32_t)((nh * 32 + nb * 16) * ROWB);
                    ldsm_x4(&bh8[nb * 4], bBase + T_BH + nrow + bOff + kb);
                    ldsm_x4(&bl8[nb * 4], bBase + T_BL + nrow + bOff + kb);
                }
                #pragma unroll
                for (int mi = 0; mi < 4; ++mi)
                    #pragma unroll
                    for (int nj = 0; nj < 4; ++nj) {
                        float* a4 = acc[mi][nh * 4 + nj];
                        mma16816(a4, ah[mi],  &bh8[nj * 2]);
                        mma16816(a4, ah[mi],  &bl8[nj * 2]);
                        mma16816(a4, al4[mi], &bh8[nj * 2]);
                    }
            }
        }
        __syncthreads();
        cur = (cur == 2) ? 0 : cur + 1;
        nxt = (nxt == 2) ? 0 : nxt + 1;
    }

    // ---- epilogue ----
    const int rowA = mBase + wm + (lid >> 2);
    const int colA = nBase + wn + (lid & 3) * 2;
    #pragma unroll
    for (int mi = 0; mi < 4; ++mi) {
        #pragma unroll
        for (int half = 0; half < 2; ++half) {
            const int row = rowA + mi * 16 + half * 8;
            #pragma unroll
            for (int ni = 0; ni < 8; ++ni) {
                const int col = colA + ni * 8;
                const float v0 = acc[mi][ni][half * 2 + 0];
                const float v1 = acc[mi][ni][half * 2 + 1];
                if (EPI == 0) {
                    float2 v; v.x = v0; v.y = v1;
                    *(float2*)(C + (long)b * sC + (long)row * Nc + col) = v;
                } else if (EPI == 1) {
                    const __nv_bfloat16 h0 = __float2bfloat16_rn(v0);
                    const __nv_bfloat16 h1 = __float2bfloat16_rn(v1);
                    __nv_bfloat162 ph, pl;
                    ph.x = h0; ph.y = h1;
                    pl.x = __float2bfloat16_rn(v0 - __bfloat162float(h0));
                    pl.y = __float2bfloat16_rn(v1 - __bfloat162float(h1));
                    *(__nv_bfloat162*)(Ch + (long)b * sC + (long)row * Nc + col) = ph;
                    *(__nv_bfloat162*)(Cl + (long)b * sC + (long)row * Nc + col) = pl;
                } else {
                    float2 v; v.x = v0; v.y = v1;
                    *(float2*)(C + (long)b * sC + (long)row * Nc + col) = v;
                    const float2 t = *(const float2*)(text + (long)b * sT + (long)row * Nc + col);
                    float2 f; f.x = v.x + t.x; f.y = v.y + t.y;
                    *(float2*)(feat + (long)b * sT + (long)row * Nc + col) = f;
                }
            }
        }
    }
}

// ---------------- fp32 -> bf16 hi/lo split ----------------
__global__ void split_kernel(const float* __restrict__ s, __nv_bfloat16* __restrict__ h,
                             __nv_bfloat16* __restrict__ l, int n4)
{
    const int i = blockIdx.x * blockDim.x + threadIdx.x;
    if (i >= n4) return;
    const float4 v = ((const float4*)s)[i];
    __nv_bfloat16 h0 = __float2bfloat16_rn(v.x), h1 = __float2bfloat16_rn(v.y);
    __nv_bfloat16 h2 = __float2bfloat16_rn(v.z), h3 = __float2bfloat16_rn(v.w);
    union { uint2 u; __nv_bfloat16 q[4]; } ph, pl;
    ph.q[0] = h0; ph.q[1] = h1; ph.q[2] = h2; ph.q[3] = h3;
    pl.q[0] = __float2bfloat16_rn(v.x - __bfloat162float(h0));
    pl.q[1] = __float2bfloat16_rn(v.y - __bfloat162float(h1));
    pl.q[2] = __float2bfloat16_rn(v.z - __bfloat162float(h2));
    pl.q[3] = __float2bfloat16_rn(v.w - __bfloat162float(h3));
    ((uint2*)h)[i] = ph.u;
    ((uint2*)l)[i] = pl.u;
}

// ---------------- V transpose + split: V[b][n][d] -> Vt[b][d][n] ----------------
__global__ void vtrans_kernel(const float* __restrict__ V,
                              __nv_bfloat16* __restrict__ Th, __nv_bfloat16* __restrict__ Tl)
{
    __shared__ float t[32][33];
    const int b = blockIdx.z;
    const float* Vb = V + (size_t)b * SEQ * DIM;
    const int n0 = blockIdx.x * 32, d0 = blockIdx.y * 32;
    #pragma unroll
    for (int r = threadIdx.y; r < 32; r += 8)
        t[r][threadIdx.x] = Vb[(size_t)(n0 + r) * DIM + d0 + threadIdx.x];
    __syncthreads();
    __nv_bfloat16* Thb = Th + (size_t)b * DIM * SEQ;
    __nv_bfloat16* Tlb = Tl + (size_t)b * DIM * SEQ;
    #pragma unroll
    for (int r = threadIdx.y; r < 32; r += 8) {
        const float v = t[threadIdx.x][r];
        const __nv_bfloat16 h = __float2bfloat16_rn(v);
        Thb[(size_t)(d0 + r) * SEQ + n0 + threadIdx.x] = h;
        Tlb[(size_t)(d0 + r) * SEQ + n0 + threadIdx.x] = __float2bfloat16_rn(v - __bfloat162float(h));
    }
}

// ---------------- softmax over QUERY axis (n of S[b][n][m]); writes split bf16 alpha ----------------
__global__ void softmax_cols_kernel(const float* __restrict__ S,
                                    __nv_bfloat16* __restrict__ Ah, __nv_bfloat16* __restrict__ Al)
{
    const int b = blockIdx.y;
    const int m = blockIdx.x * blockDim.x + threadIdx.x;
    const float* Sb = S + (size_t)b * SEQ * SEQ;
    __nv_bfloat16* Ahb = Ah + (size_t)b * SEQ * SEQ;
    __nv_bfloat16* Alb = Al + (size_t)b * SEQ * SEQ;

    float mx = -3.4e38f, s = 0.f;
    for (int n = 0; n < SEQ; ++n) {
        const float x = Sb[(size_t)n * SEQ + m];
        const float nm = fmaxf(mx, x);
        s = s * __expf(mx - nm) + __expf(x - nm);
        mx = nm;
    }
    const float inv = 1.f / s;
    for (int n = 0; n < SEQ; ++n) {
        const float x = Sb[(size_t)n * SEQ + m];
        const float a = __expf(x - mx) * inv;
        const __nv_bfloat16 h = __float2bfloat16_rn(a);
        Ahb[(size_t)n * SEQ + m] = h;
        Alb[(size_t)n * SEQ + m] = __float2bfloat16_rn(a - __bfloat162float(h));
    }
}

// ---------------- launch ----------------
extern "C" void kernel_launch(void* const* d_in, const int* in_sizes, int n_in,
                              void* d_out, int out_size)
{
    const float* img  = (const float*)d_in[0];
    const float* text = (const float*)d_in[1];
    const float* Wq   = (const float*)d_in[2];
    const float* Wk   = (const float*)d_in[3];
    const float* Wv   = (const float*)d_in[4];

    float* out  = (float*)d_out;
    float* feat = out + (size_t)MT * DIM;

    __nv_bfloat16 *imgh, *imgl, *texth, *textl, *wqh, *wql, *wkh, *wkl, *wvh, *wvl;
    __nv_bfloat16 *qh, *ql, *kh, *kl, *vth, *vtl, *ah, *al;
    float *v, *s;
    cudaGetSymbolAddress((void**)&imgh, g_img_h);  cudaGetSymbolAddress((void**)&imgl, g_img_l);
    cudaGetSymbolAddress((void**)&texth, g_text_h); cudaGetSymbolAddress((void**)&textl, g_text_l);
    cudaGetSymbolAddress((void**)&wqh, g_Wq_h);    cudaGetSymbolAddress((void**)&wql, g_Wq_l);
    cudaGetSymbolAddress((void**)&wkh, g_Wk_h);    cudaGetSymbolAddress((void**)&wkl, g_Wk_l);
    cudaGetSymbolAddress((void**)&wvh, g_Wv_h);    cudaGetSymbolAddress((void**)&wvl, g_Wv_l);
    cudaGetSymbolAddress((void**)&qh, g_Qh);       cudaGetSymbolAddress((void**)&ql, g_Ql);
    cudaGetSymbolAddress((void**)&kh, g_Kh);       cudaGetSymbolAddress((void**)&kl, g_Kl);
    cudaGetSymbolAddress((void**)&v, g_V);
    cudaGetSymbolAddress((void**)&vth, g_Vth);     cudaGetSymbolAddress((void**)&vtl, g_Vtl);
    cudaGetSymbolAddress((void**)&s, g_S);
    cudaGetSymbolAddress((void**)&ah, g_Ah);       cudaGetSymbolAddress((void**)&al, g_Al);

    cudaFuncSetAttribute(gemm_hmma3<0>, cudaFuncAttributeMaxDynamicSharedMemorySize, SMEM_TOTAL);
    cudaFuncSetAttribute(gemm_hmma3<1>, cudaFuncAttributeMaxDynamicSharedMemorySize, SMEM_TOTAL);
    cudaFuncSetAttribute(gemm_hmma3<2>, cudaFuncAttributeMaxDynamicSharedMemorySize, SMEM_TOTAL);

    const long nd = (long)SEQ * DIM;    // 2 M
    const long nn = (long)SEQ * SEQ;    // 4 M

    // 1. split inputs
    {
        const int n4i = MT * DIM / 4;
        split_kernel<<<n4i / 256, 256>>>(img,  imgh,  imgl,  n4i);
        split_kernel<<<n4i / 256, 256>>>(text, texth, textl, n4i);
        const int n4w = DIM * DIM / 4;
        split_kernel<<<n4w / 256, 256>>>(Wq, wqh, wql, n4w);
        split_kernel<<<n4w / 256, 256>>>(Wk, wkh, wkl, n4w);
        split_kernel<<<n4w / 256, 256>>>(Wv, wvh, wvl, n4w);
    }

    // 2. projections: [16384,1024] = X @ W^T
    {
        dim3 g(DIM / 256, MT / 128, 1), blk(256);
        gemm_hmma3<1><<<g, blk, SMEM_TOTAL>>>(imgh, imgl, wqh, wql, MT, DIM, DIM, 0, 0, 0,
                                              nullptr, qh, ql, nullptr, nullptr, 0);
        gemm_hmma3<1><<<g, blk, SMEM_TOTAL>>>(texth, textl, wkh, wkl, MT, DIM, DIM, 0, 0, 0,
                                              nullptr, kh, kl, nullptr, nullptr, 0);
        gemm_hmma3<0><<<g, blk, SMEM_TOTAL>>>(texth, textl, wvh, wvl, MT, DIM, DIM, 0, 0, 0,
                                              v, nullptr, nullptr, nullptr, nullptr, 0);
    }

    // 3. transpose + split V
    {
        dim3 g(SEQ / 32, DIM / 32, BB), blk(32, 8);
        vtrans_kernel<<<g, blk>>>(v, vth, vtl);
    }

    // 4. scores: per batch S[2048,2048] = Q @ K^T
    {
        dim3 g(SEQ / 256, SEQ / 128, BB), blk(256);
        gemm_hmma3<0><<<g, blk, SMEM_TOTAL>>>(qh, ql, kh, kl, SEQ, SEQ, DIM, nd, nd, nn,
                                              s, nullptr, nullptr, nullptr, nullptr, 0);
    }

    // 5. softmax over query axis, write split bf16 alpha
    {
        dim3 g(SEQ / 256, BB), blk(256);
        softmax_cols_kernel<<<g, blk>>>(s, ah, al);
    }

    // 6. out = alpha @ V ;  feature = out + text
    {
        dim3 g(DIM / 256, SEQ / 128, BB), blk(256);
        gemm_hmma3<2><<<g, blk, SMEM_TOTAL>>>(ah, al, vth, vtl, SEQ, DIM, SEQ, nn, nd, nd,
                                              out, nullptr, nullptr, text, feat, nd);
    }
}

// round 7
// speedup vs baseline: 2.9880x; 1.2476x over previous
#include <cuda_runtime.h>
#include <cuda_fp16.h>
#include <cstdint>

// ---------------- problem constants ----------------
#define BB   8
#define SEQ  2048
#define DIM  1024
#define MT   (BB * SEQ)          // 16384 flattened rows

// ---------------- PTX helpers (base-target legal, sm_80+) ----------------
__device__ __forceinline__ uint32_t smem_to_u32(const void* p) {
    uint32_t a;
    asm("{ .reg .u64 t; cvta.to.shared.u64 t, %1; cvt.u32.u64 %0, t; }" : "=r"(a) : "l"(p));
    return a;
}
#define CP_ASYNC16(dst, src) \
    asm volatile("cp.async.cg.shared.global [%0], [%1], 16;" :: "r"(dst), "l"(src))
#define CP_COMMIT() asm volatile("cp.async.commit_group;" ::: "memory")
#define CP_WAIT2()  asm volatile("cp.async.wait_group 2;" ::: "memory")
#define CP_WAIT1()  asm volatile("cp.async.wait_group 1;" ::: "memory")
#define CP_WAIT0()  asm volatile("cp.async.wait_group 0;" ::: "memory")

__device__ __forceinline__ void ldsm_x4(uint32_t* r, uint32_t addr) {
    asm volatile("ldmatrix.sync.aligned.m8n8.x4.shared.b16 {%0,%1,%2,%3}, [%4];"
                 : "=r"(r[0]), "=r"(r[1]), "=r"(r[2]), "=r"(r[3]) : "r"(addr));
}
__device__ __forceinline__ void mma16816(float* c, const uint32_t* a, const uint32_t* b) {
    asm volatile(
        "mma.sync.aligned.m16n8k16.row.col.f32.f16.f16.f32 "
        "{%0,%1,%2,%3}, {%4,%5,%6,%7}, {%8,%9}, {%0,%1,%2,%3};"
        : "+f"(c[0]), "+f"(c[1]), "+f"(c[2]), "+f"(c[3])
        : "r"(a[0]), "r"(a[1]), "r"(a[2]), "r"(a[3]), "r"(b[0]), "r"(b[1]));
}

// ---------------- scratch (no cudaMalloc allowed) ----------------
__device__ __half g_img_h[(size_t)MT * DIM], g_img_l[(size_t)MT * DIM];
__device__ __half g_text_h[(size_t)MT * DIM], g_text_l[(size_t)MT * DIM];
__device__ __half g_Wqt_h[(size_t)DIM * DIM], g_Wqt_l[(size_t)DIM * DIM];   // Wq^T [d,i]
__device__ __half g_Wkt_h[(size_t)DIM * DIM], g_Wkt_l[(size_t)DIM * DIM];   // Wk^T [e,i]
__device__ __half g_Wv_h[(size_t)DIM * DIM], g_Wv_l[(size_t)DIM * DIM];
__device__ __half g_Gt_h[(size_t)DIM * DIM], g_Gt_l[(size_t)DIM * DIM];     // G^T [e,d]
__device__ __half g_U_h[(size_t)MT * DIM], g_U_l[(size_t)MT * DIM];         // img @ G
__device__ float  g_V[(size_t)MT * DIM];
__device__ __half g_Vth[(size_t)MT * DIM], g_Vtl[(size_t)MT * DIM];         // [B][DIM][SEQ]
__device__ float  g_S[(size_t)BB * SEQ * SEQ];
__device__ __half g_Ah[(size_t)BB * SEQ * SEQ];

// ---------------- GEMM: C[M,Nc] ~= (A0[+A1]) @ (B0[+B1])^T, fp16 HMMA ----------------
// Terms: A0B0 always; A0B1 if TB==2; A1B0 if TA==2 (A1B1 dropped).
// BM=128, BN=256, BK=32, 3-stage cp.async, warp tile 64x64 (8 warps 2x4).
// SMEM rows 80B (64B data + 16 pad) -> conflict-free ldmatrix & cp.async.
#define ROWB     80
#define TILEB_A  (128 * ROWB)            // 10240
#define TILEB_B  (256 * ROWB)            // 20480

template<int TA, int TB, int EPI>   // EPI 0: fp32 C   1: split fp16 Ch/Cl   2: fp32 C + feat=C+text
__global__ void __launch_bounds__(256, 1)
gemm_h(const __half* __restrict__ A0, const __half* __restrict__ A1,
       const __half* __restrict__ B0, const __half* __restrict__ B1,
       int M, int Nc, int Kd, long sA, long sB, long sC,
       float* __restrict__ C, __half* __restrict__ Ch, __half* __restrict__ Cl,
       const float* __restrict__ text, float* __restrict__ feat, long sT)
{
    constexpr uint32_t T_A0 = 0;
    constexpr uint32_t T_A1 = TILEB_A;                 // valid iff TA==2
    constexpr uint32_t T_B0 = TA * TILEB_A;
    constexpr uint32_t T_B1 = T_B0 + TILEB_B;          // valid iff TB==2
    constexpr uint32_t STAGE_SZ = TA * TILEB_A + TB * TILEB_B;

    extern __shared__ char smem[];
    const uint32_t sbase = smem_to_u32(smem);
    const int tid = threadIdx.x;
    const int wid = tid >> 5;
    const int lid = tid & 31;
    const int b = blockIdx.z;

    const int mBase = blockIdx.y * 128;
    const int nBase = blockIdx.x * 256;

    const __half* gA0 = A0 + (long)b * sA + (long)mBase * Kd;
    const __half* gA1 = (TA == 2) ? A1 + (long)b * sA + (long)mBase * Kd : nullptr;
    const __half* gB0 = B0 + (long)b * sB + (long)nBase * Kd;
    const __half* gB1 = (TB == 2) ? B1 + (long)b * sB + (long)nBase * Kd : nullptr;

    auto load_stage = [&](int k0, int s) {
        const uint32_t st = sbase + (uint32_t)s * STAGE_SZ;
        #pragma unroll
        for (int c = 0; c < 2; ++c) {          // A: 512 16B chunks per tile
            const int ch = tid + c * 256;
            const int r = ch >> 2, col = (ch & 3) * 16;
            CP_ASYNC16(st + T_A0 + r * ROWB + col, (const char*)(gA0 + (long)r * Kd + k0) + col);
            if (TA == 2)
                CP_ASYNC16(st + T_A1 + r * ROWB + col, (const char*)(gA1 + (long)r * Kd + k0) + col);
        }
        #pragma unroll
        for (int c = 0; c < 4; ++c) {          // B: 1024 chunks per tile
            const int ch = tid + c * 256;
            const int r = ch >> 2, col = (ch & 3) * 16;
            CP_ASYNC16(st + T_B0 + r * ROWB + col, (const char*)(gB0 + (long)r * Kd + k0) + col);
            if (TB == 2)
                CP_ASYNC16(st + T_B1 + r * ROWB + col, (const char*)(gB1 + (long)r * Kd + k0) + col);
        }
    };

    const int wm = (wid >> 2) * 64;
    const int wn = (wid & 3) * 64;

    const uint32_t aOff = (uint32_t)((lid & 15) * ROWB + (lid >> 4) * 16);
    const uint32_t bOff = (uint32_t)((((lid >> 4) << 3) + (lid & 7)) * ROWB + ((lid >> 3) & 1) * 16);

    float acc[4][8][4];
    #pragma unroll
    for (int mi = 0; mi < 4; ++mi)
        #pragma unroll
        for (int ni = 0; ni < 8; ++ni)
            #pragma unroll
            for (int q = 0; q < 4; ++q) acc[mi][ni][q] = 0.f;

    const int nch = Kd >> 5;

    load_stage(0, 0);  CP_COMMIT();
    load_stage(32, 1); CP_COMMIT();

    int cur = 0, nxt = 2;
    for (int i = 0; i < nch; ++i) {
        if (i + 2 < nch)      { load_stage((i + 2) << 5, nxt); CP_COMMIT(); CP_WAIT2(); }
        else if (i + 1 < nch) { CP_WAIT1(); }
        else                  { CP_WAIT0(); }
        __syncthreads();

        const uint32_t st = sbase + (uint32_t)cur * STAGE_SZ;
        const uint32_t aBase = st + (uint32_t)(wm * ROWB);
        const uint32_t bBase = st + (uint32_t)(wn * ROWB);

        #pragma unroll
        for (int kk = 0; kk < 2; ++kk) {
            const uint32_t kb = kk * 32;
            uint32_t a0r[4][4], a1r[4][4];
            #pragma unroll
            for (int mi = 0; mi < 4; ++mi) {
                ldsm_x4(a0r[mi], aBase + T_A0 + (uint32_t)(mi * 16 * ROWB) + aOff + kb);
                if (TA == 2)
                    ldsm_x4(a1r[mi], aBase + T_A1 + (uint32_t)(mi * 16 * ROWB) + aOff + kb);
            }
            #pragma unroll
            for (int nh = 0; nh < 2; ++nh) {
                uint32_t b0r[8], b1r[8];
                #pragma unroll
                for (int nb = 0; nb < 2; ++nb) {
                    const uint32_t nrow = (uint32_t)((nh * 32 + nb * 16) * ROWB);
                    ldsm_x4(&b0r[nb * 4], bBase + T_B0 + nrow + bOff + kb);
                    if (TB == 2)
                        ldsm_x4(&b1r[nb * 4], bBase + T_B1 + nrow + bOff + kb);
                }
                #pragma unroll
                for (int mi = 0; mi < 4; ++mi)
                    #pragma unroll
                    for (int nj = 0; nj < 4; ++nj) {
                        float* a4 = acc[mi][nh * 4 + nj];
                        mma16816(a4, a0r[mi], &b0r[nj * 2]);
                        if (TB == 2) mma16816(a4, a0r[mi], &b1r[nj * 2]);
                        if (TA == 2) mma16816(a4, a1r[mi], &b0r[nj * 2]);
                    }
            }
        }
        __syncthreads();
        cur = (cur == 2) ? 0 : cur + 1;
        nxt = (nxt == 2) ? 0 : nxt + 1;
    }

    // ---- epilogue ----
    const int rowA = mBase + wm + (lid >> 2);
    const int colA = nBase + wn + (lid & 3) * 2;
    #pragma unroll
    for (int mi = 0; mi < 4; ++mi) {
        #pragma unroll
        for (int half = 0; half < 2; ++half) {
            const int row = rowA + mi * 16 + half * 8;
            #pragma unroll
            for (int ni = 0; ni < 8; ++ni) {
                const int col = colA + ni * 8;
                const float v0 = acc[mi][ni][half * 2 + 0];
                const float v1 = acc[mi][ni][half * 2 + 1];
                if (EPI == 0) {
                    float2 v; v.x = v0; v.y = v1;
                    *(float2*)(C + (long)b * sC + (long)row * Nc + col) = v;
                } else if (EPI == 1) {
                    const __half h0 = __float2half_rn(v0);
                    const __half h1 = __float2half_rn(v1);
                    __half2 ph, pl;
                    ph.x = h0; ph.y = h1;
                    pl.x = __float2half_rn(v0 - __half2float(h0));
                    pl.y = __float2half_rn(v1 - __half2float(h1));
                    *(__half2*)(Ch + (long)b * sC + (long)row * Nc + col) = ph;
                    *(__half2*)(Cl + (long)b * sC + (long)row * Nc + col) = pl;
                } else {
                    float2 v; v.x = v0; v.y = v1;
                    *(float2*)(C + (long)b * sC + (long)row * Nc + col) = v;
                    const float2 t = *(const float2*)(text + (long)b * sT + (long)row * Nc + col);
                    float2 f; f.x = v.x + t.x; f.y = v.y + t.y;
                    *(float2*)(feat + (long)b * sT + (long)row * Nc + col) = f;
                }
            }
        }
    }
}

// ---------------- fp32 -> fp16 hi/lo split ----------------
__global__ void split_kernel(const float* __restrict__ s, __half* __restrict__ h,
                             __half* __restrict__ l, int n4)
{
    const int i = blockIdx.x * blockDim.x + threadIdx.x;
    if (i >= n4) return;
    const float4 v = ((const float4*)s)[i];
    union { uint2 u; __half q[4]; } ph, pl;
    #pragma unroll
    for (int q = 0; q < 4; ++q) {
        const float x = (&v.x)[q];
        const __half hh = __float2half_rn(x);
        ph.q[q] = hh;
        pl.q[q] = __float2half_rn(x - __half2float(hh));
    }
    ((uint2*)h)[i] = ph.u;
    ((uint2*)l)[i] = pl.u;
}

// ---------------- transpose + split: A[R,C] fp32 -> Th/Tl[C,R] fp16 ----------------
__global__ void tsplit_kernel(const float* __restrict__ A,
                              __half* __restrict__ Th, __half* __restrict__ Tl, int R, int C)
{
    __shared__ float t[32][33];
    const int r0 = blockIdx.x * 32, c0 = blockIdx.y * 32;
    #pragma unroll
    for (int r = threadIdx.y; r < 32; r += 8)
        t[r][threadIdx.x] = A[(size_t)(r0 + r) * C + c0 + threadIdx.x];
    __syncthreads();
    #pragma unroll
    for (int r = threadIdx.y; r < 32; r += 8) {
        const float v = t[threadIdx.x][r];
        const __half h = __float2half_rn(v);
        Th[(size_t)(c0 + r) * R + r0 + threadIdx.x] = h;
        Tl[(size_t)(c0 + r) * R + r0 + threadIdx.x] = __float2half_rn(v - __half2float(h));
    }
}

// ---------------- V transpose + split: V[b][n][d] -> Vt[b][d][n] fp16 h/l ----------------
__global__ void vtrans_kernel(const float* __restrict__ V,
                              __half* __restrict__ Th, __half* __restrict__ Tl)
{
    __shared__ float t[32][33];
    const int b = blockIdx.z;
    const float* Vb = V + (size_t)b * SEQ * DIM;
    const int n0 = blockIdx.x * 32, d0 = blockIdx.y * 32;
    #pragma unroll
    for (int r = threadIdx.y; r < 32; r += 8)
        t[r][threadIdx.x] = Vb[(size_t)(n0 + r) * DIM + d0 + threadIdx.x];
    __syncthreads();
    __half* Thb = Th + (size_t)b * DIM * SEQ;
    __half* Tlb = Tl + (size_t)b * DIM * SEQ;
    #pragma unroll
    for (int r = threadIdx.y; r < 32; r += 8) {
        const float v = t[threadIdx.x][r];
        const __half h = __float2half_rn(v);
        Thb[(size_t)(d0 + r) * SEQ + n0 + threadIdx.x] = h;
        Tlb[(size_t)(d0 + r) * SEQ + n0 + threadIdx.x] = __float2half_rn(v - __half2float(h));
    }
}

// ---------------- softmax over QUERY axis (n of S[b][n][m]); writes fp16 alpha ----------------
__global__ void softmax_cols_kernel(const float* __restrict__ S, __half* __restrict__ Ah)
{
    const int b = blockIdx.y;
    const int m = blockIdx.x * blockDim.x + threadIdx.x;
    const float* Sb = S + (size_t)b * SEQ * SEQ;
    __half* Ahb = Ah + (size_t)b * SEQ * SEQ;

    float mx = -3.4e38f, s = 0.f;
    for (int n = 0; n < SEQ; ++n) {
        const float x = Sb[(size_t)n * SEQ + m];
        const float nm = fmaxf(mx, x);
        s = s * __expf(mx - nm) + __expf(x - nm);
        mx = nm;
    }
    const float inv = 1.f / s;
    for (int n = 0; n < SEQ; ++n) {
        const float x = Sb[(size_t)n * SEQ + m];
        Ahb[(size_t)n * SEQ + m] = __float2half_rn(__expf(x - mx) * inv);
    }
}

// ---------------- launch ----------------
extern "C" void kernel_launch(void* const* d_in, const int* in_sizes, int n_in,
                              void* d_out, int out_size)
{
    const float* img  = (const float*)d_in[0];
    const float* text = (const float*)d_in[1];
    const float* Wq   = (const float*)d_in[2];
    const float* Wk   = (const float*)d_in[3];
    const float* Wv   = (const float*)d_in[4];

    float* out  = (float*)d_out;
    float* feat = out + (size_t)MT * DIM;

    __half *imgh, *imgl, *texth, *textl, *wqth, *wqtl, *wkth, *wktl, *wvh, *wvl;
    __half *gth, *gtl, *uh, *ul, *vth, *vtl, *ah;
    float *v, *s;
    cudaGetSymbolAddress((void**)&imgh, g_img_h);   cudaGetSymbolAddress((void**)&imgl, g_img_l);
    cudaGetSymbolAddress((void**)&texth, g_text_h); cudaGetSymbolAddress((void**)&textl, g_text_l);
    cudaGetSymbolAddress((void**)&wqth, g_Wqt_h);   cudaGetSymbolAddress((void**)&wqtl, g_Wqt_l);
    cudaGetSymbolAddress((void**)&wkth, g_Wkt_h);   cudaGetSymbolAddress((void**)&wktl, g_Wkt_l);
    cudaGetSymbolAddress((void**)&wvh, g_Wv_h);     cudaGetSymbolAddress((void**)&wvl, g_Wv_l);
    cudaGetSymbolAddress((void**)&gth, g_Gt_h);     cudaGetSymbolAddress((void**)&gtl, g_Gt_l);
    cudaGetSymbolAddress((void**)&uh, g_U_h);       cudaGetSymbolAddress((void**)&ul, g_U_l);
    cudaGetSymbolAddress((void**)&v, g_V);
    cudaGetSymbolAddress((void**)&vth, g_Vth);      cudaGetSymbolAddress((void**)&vtl, g_Vtl);
    cudaGetSymbolAddress((void**)&s, g_S);
    cudaGetSymbolAddress((void**)&ah, g_Ah);

    constexpr int SM33 = 3 * (2 * TILEB_A + 2 * TILEB_B);  // 184320
    constexpr int SM21 = 3 * (2 * TILEB_A + 1 * TILEB_B);  // 122880
    constexpr int SM12 = 3 * (1 * TILEB_A + 2 * TILEB_B);  // 153600
    cudaFuncSetAttribute(gemm_h<2,2,0>, cudaFuncAttributeMaxDynamicSharedMemorySize, SM33);
    cudaFuncSetAttribute(gemm_h<2,2,1>, cudaFuncAttributeMaxDynamicSharedMemorySize, SM33);
    cudaFuncSetAttribute(gemm_h<2,1,0>, cudaFuncAttributeMaxDynamicSharedMemorySize, SM21);
    cudaFuncSetAttribute(gemm_h<1,2,2>, cudaFuncAttributeMaxDynamicSharedMemorySize, SM12);

    const long nd = (long)SEQ * DIM;    // 2 M
    const long nn = (long)SEQ * SEQ;    // 4 M
    dim3 blk(256);

    // 1. split img/text; split Wv; transpose-split Wq, Wk
    {
        const int n4i = MT * DIM / 4;
        split_kernel<<<n4i / 256, 256>>>(img,  imgh,  imgl,  n4i);
        split_kernel<<<n4i / 256, 256>>>(text, texth, textl, n4i);
        const int n4w = DIM * DIM / 4;
        split_kernel<<<n4w / 256, 256>>>(Wv, wvh, wvl, n4w);
        dim3 gt(DIM / 32, DIM / 32), bt(32, 8);
        tsplit_kernel<<<gt, bt>>>(Wq, wqth, wqtl, DIM, DIM);  // Wqt[d,i]
        tsplit_kernel<<<gt, bt>>>(Wk, wkth, wktl, DIM, DIM);  // Wkt[e,i]
    }

    // 2. Gt[e,d] = sum_i Wkt[e,i] * Wqt[d,i]   (3-term, split fp16 out)
    {
        dim3 g(DIM / 256, DIM / 128, 1);
        gemm_h<2,2,1><<<g, blk, SM33>>>(wkth, wktl, wqth, wqtl, DIM, DIM, DIM, 0, 0, 0,
                                        nullptr, gth, gtl, nullptr, nullptr, 0);
    }

    // 3. U[n,e] = sum_d img[n,d] * Gt[e,d]   (3-term, split fp16 out)
    //    V[n,i] = sum_e text[n,e] * Wv[i,e]  (2-term: text 2-limb x Wv hi)
    {
        dim3 g(DIM / 256, MT / 128, 1);
        gemm_h<2,2,1><<<g, blk, SM33>>>(imgh, imgl, gth, gtl, MT, DIM, DIM, 0, 0, 0,
                                        nullptr, uh, ul, nullptr, nullptr, 0);
        gemm_h<2,1,0><<<g, blk, SM21>>>(texth, textl, wvh, nullptr, MT, DIM, DIM, 0, 0, 0,
                                        v, nullptr, nullptr, nullptr, nullptr, 0);
    }

    // 4. transpose + split V
    {
        dim3 g(SEQ / 32, DIM / 32, BB), bt(32, 8);
        vtrans_kernel<<<g, bt>>>(v, vth, vtl);
    }

    // 5. scores: per batch S[n,m] = sum_e U[n,e] * text[m,e]   (3-term)
    {
        dim3 g(SEQ / 256, SEQ / 128, BB);
        gemm_h<2,2,0><<<g, blk, SM33>>>(uh, ul, texth, textl, SEQ, SEQ, DIM, nd, nd, nn,
                                        s, nullptr, nullptr, nullptr, nullptr, 0);
    }

    // 6. softmax over query axis -> fp16 alpha
    {
        dim3 g(SEQ / 256, BB);
        softmax_cols_kernel<<<g, blk>>>(s, ah);
    }

    // 7. out = alpha @ V (2-term: alpha hi x Vt 2-limb); feature = out + text
    {
        dim3 g(DIM / 256, SEQ / 128, BB);
        gemm_h<1,2,2><<<g, blk, SM12>>>(ah, nullptr, vth, vtl, SEQ, DIM, SEQ, nn, nd, nd,
                                        out, nullptr, nullptr, text, feat, nd);
    }
}

// round 12
// speedup vs baseline: 3.3089x; 1.1074x over previous
#include <cuda_runtime.h>
#include <cuda_fp16.h>
#include <cstdint>

// ---------------- problem constants ----------------
#define BB   8
#define SEQ  2048
#define DIM  1024
#define MT   (BB * SEQ)          // 16384 flattened rows

// ---------------- PTX helpers (base-target legal, sm_80+) ----------------
__device__ __forceinline__ uint32_t smem_to_u32(const void* p) {
    uint32_t a;
    asm("{ .reg .u64 t; cvta.to.shared.u64 t, %1; cvt.u32.u64 %0, t; }" : "=r"(a) : "l"(p));
    return a;
}
#define CP_ASYNC16(dst, src) \
    asm volatile("cp.async.cg.shared.global [%0], [%1], 16;" :: "r"(dst), "l"(src))
#define CP_COMMIT() asm volatile("cp.async.commit_group;" ::: "memory")
#define CP_WAIT2()  asm volatile("cp.async.wait_group 2;" ::: "memory")
#define CP_WAIT1()  asm volatile("cp.async.wait_group 1;" ::: "memory")
#define CP_WAIT0()  asm volatile("cp.async.wait_group 0;" ::: "memory")

__device__ __forceinline__ void ldsm_x4(uint32_t* r, uint32_t addr) {
    asm volatile("ldmatrix.sync.aligned.m8n8.x4.shared.b16 {%0,%1,%2,%3}, [%4];"
                 : "=r"(r[0]), "=r"(r[1]), "=r"(r[2]), "=r"(r[3]) : "r"(addr));
}
__device__ __forceinline__ void mma16816(float* c, const uint32_t* a, const uint32_t* b) {
    asm volatile(
        "mma.sync.aligned.m16n8k16.row.col.f32.f16.f16.f32 "
        "{%0,%1,%2,%3}, {%4,%5,%6,%7}, {%8,%9}, {%0,%1,%2,%3};"
        : "+f"(c[0]), "+f"(c[1]), "+f"(c[2]), "+f"(c[3])
        : "r"(a[0]), "r"(a[1]), "r"(a[2]), "r"(a[3]), "r"(b[0]), "r"(b[1]));
}

// ---------------- scratch (no cudaMalloc allowed) ----------------
__device__ __half g_img_h[(size_t)MT * DIM], g_img_l[(size_t)MT * DIM];
__device__ __half g_text_h[(size_t)MT * DIM], g_text_l[(size_t)MT * DIM];
__device__ __half g_Wqt_h[(size_t)DIM * DIM], g_Wqt_l[(size_t)DIM * DIM];   // Wq^T [d,i]
__device__ __half g_Wkt_h[(size_t)DIM * DIM], g_Wkt_l[(size_t)DIM * DIM];   // Wk^T [e,i]
__device__ __half g_Wv_h[(size_t)DIM * DIM];
__device__ __half g_Gt_h[(size_t)DIM * DIM], g_Gt_l[(size_t)DIM * DIM];     // G^T [e,d]
__device__ __half g_U_h[(size_t)MT * DIM], g_U_l[(size_t)MT * DIM];         // img @ G
__device__ float  g_V[(size_t)MT * DIM];
__device__ __half g_Vth[(size_t)MT * DIM];                                   // [B][DIM][SEQ]
__device__ float  g_S[(size_t)BB * SEQ * SEQ];
__device__ __half g_Ah[(size_t)BB * SEQ * SEQ];

// ---------------- GEMM: C[M,Nc] ~= (A0[+A1]) @ (B0[+B1])^T, fp16 HMMA ----------------
// Terms: A0B0 always; A0B1 if TB==2; A1B0 if TA==2 (A1B1 dropped).
// BM=128, BN=256, BK=32, 3-stage cp.async, warp tile 64x64 (8 warps 2x4).
// SMEM rows 80B (64B data + 16 pad) -> conflict-free ldmatrix & cp.async.
#define ROWB     80
#define TILEB_A  (128 * ROWB)            // 10240
#define TILEB_B  (256 * ROWB)            // 20480

template<int TA, int TB, int EPI>   // EPI 0: fp32 C   1: split fp16 Ch/Cl   2: fp32 C + feat=C+text
__global__ void __launch_bounds__(256, 1)
gemm_h(const __half* __restrict__ A0, const __half* __restrict__ A1,
       const __half* __restrict__ B0, const __half* __restrict__ B1,
       int M, int Nc, int Kd, long sA, long sB, long sC,
       float* __restrict__ C, __half* __restrict__ Ch, __half* __restrict__ Cl,
       const float* __restrict__ text, float* __restrict__ feat, long sT)
{
    constexpr uint32_t T_A0 = 0;
    constexpr uint32_t T_A1 = TILEB_A;                 // valid iff TA==2
    constexpr uint32_t T_B0 = TA * TILEB_A;
    constexpr uint32_t T_B1 = T_B0 + TILEB_B;          // valid iff TB==2
    constexpr uint32_t STAGE_SZ = TA * TILEB_A + TB * TILEB_B;

    extern __shared__ char smem[];
    const uint32_t sbase = smem_to_u32(smem);
    const int tid = threadIdx.x;
    const int wid = tid >> 5;
    const int lid = tid & 31;
    const int b = blockIdx.z;

    const int mBase = blockIdx.y * 128;
    const int nBase = blockIdx.x * 256;

    const __half* gA0 = A0 + (long)b * sA + (long)mBase * Kd;
    const __half* gA1 = (TA == 2) ? A1 + (long)b * sA + (long)mBase * Kd : nullptr;
    const __half* gB0 = B0 + (long)b * sB + (long)nBase * Kd;
    const __half* gB1 = (TB == 2) ? B1 + (long)b * sB + (long)nBase * Kd : nullptr;

    auto load_stage = [&](int k0, int s) {
        const uint32_t st = sbase + (uint32_t)s * STAGE_SZ;
        #pragma unroll
        for (int c = 0; c < 2; ++c) {          // A: 512 16B chunks per tile
            const int ch = tid + c * 256;
            const int r = ch >> 2, col = (ch & 3) * 16;
            CP_ASYNC16(st + T_A0 + r * ROWB + col, (const char*)(gA0 + (long)r * Kd + k0) + col);
            if (TA == 2)
                CP_ASYNC16(st + T_A1 + r * ROWB + col, (const char*)(gA1 + (long)r * Kd + k0) + col);
        }
        #pragma unroll
        for (int c = 0; c < 4; ++c) {          // B: 1024 chunks per tile
            const int ch = tid + c * 256;
            const int r = ch >> 2, col = (ch & 3) * 16;
            CP_ASYNC16(st + T_B0 + r * ROWB + col, (const char*)(gB0 + (long)r * Kd + k0) + col);
            if (TB == 2)
                CP_ASYNC16(st + T_B1 + r * ROWB + col, (const char*)(gB1 + (long)r * Kd + k0) + col);
        }
    };

    const int wm = (wid >> 2) * 64;
    const int wn = (wid & 3) * 64;

    const uint32_t aOff = (uint32_t)((lid & 15) * ROWB + (lid >> 4) * 16);
    const uint32_t bOff = (uint32_t)((((lid >> 4) << 3) + (lid & 7)) * ROWB + ((lid >> 3) & 1) * 16);

    float acc[4][8][4];
    #pragma unroll
    for (int mi = 0; mi < 4; ++mi)
        #pragma unroll
        for (int ni = 0; ni < 8; ++ni)
            #pragma unroll
            for (int q = 0; q < 4; ++q) acc[mi][ni][q] = 0.f;

    const int nch = Kd >> 5;

    load_stage(0, 0);  CP_COMMIT();
    load_stage(32, 1); CP_COMMIT();

    int cur = 0, nxt = 2;
    for (int i = 0; i < nch; ++i) {
        if (i + 2 < nch)      { load_stage((i + 2) << 5, nxt); CP_COMMIT(); CP_WAIT2(); }
        else if (i + 1 < nch) { CP_WAIT1(); }
        else                  { CP_WAIT0(); }
        __syncthreads();

        const uint32_t st = sbase + (uint32_t)cur * STAGE_SZ;
        const uint32_t aBase = st + (uint32_t)(wm * ROWB);
        const uint32_t bBase = st + (uint32_t)(wn * ROWB);

        #pragma unroll
        for (int kk = 0; kk < 2; ++kk) {
            const uint32_t kb = kk * 32;
            uint32_t a0r[4][4], a1r[4][4];
            #pragma unroll
            for (int mi = 0; mi < 4; ++mi) {
                ldsm_x4(a0r[mi], aBase + T_A0 + (uint32_t)(mi * 16 * ROWB) + aOff + kb);
                if (TA == 2)
                    ldsm_x4(a1r[mi], aBase + T_A1 + (uint32_t)(mi * 16 * ROWB) + aOff + kb);
            }
            #pragma unroll
            for (int nh = 0; nh < 2; ++nh) {
                uint32_t b0r[8], b1r[8];
                #pragma unroll
                for (int nb = 0; nb < 2; ++nb) {
                    const uint32_t nrow = (uint32_t)((nh * 32 + nb * 16) * ROWB);
                    ldsm_x4(&b0r[nb * 4], bBase + T_B0 + nrow + bOff + kb);
                    if (TB == 2)
                        ldsm_x4(&b1r[nb * 4], bBase + T_B1 + nrow + bOff + kb);
                }
                #pragma unroll
                for (int mi = 0; mi < 4; ++mi)
                    #pragma unroll
                    for (int nj = 0; nj < 4; ++nj) {
                        float* a4 = acc[mi][nh * 4 + nj];
                        mma16816(a4, a0r[mi], &b0r[nj * 2]);
                        if (TB == 2) mma16816(a4, a0r[mi], &b1r[nj * 2]);
                        if (TA == 2) mma16816(a4, a1r[mi], &b0r[nj * 2]);
                    }
            }
        }
        __syncthreads();
        cur = (cur == 2) ? 0 : cur + 1;
        nxt = (nxt == 2) ? 0 : nxt + 1;
    }

    // ---- epilogue ----
    const int rowA = mBase + wm + (lid >> 2);
    const int colA = nBase + wn + (lid & 3) * 2;
    #pragma unroll
    for (int mi = 0; mi < 4; ++mi) {
        #pragma unroll
        for (int half = 0; half < 2; ++half) {
            const int row = rowA + mi * 16 + half * 8;
            #pragma unroll
            for (int ni = 0; ni < 8; ++ni) {
                const int col = colA + ni * 8;
                const float v0 = acc[mi][ni][half * 2 + 0];
                const float v1 = acc[mi][ni][half * 2 + 1];
                if (EPI == 0) {
                    float2 v; v.x = v0; v.y = v1;
                    *(float2*)(C + (long)b * sC + (long)row * Nc + col) = v;
                } else if (EPI == 1) {
                    const __half h0 = __float2half_rn(v0);
                    const __half h1 = __float2half_rn(v1);
                    __half2 ph, pl;
                    ph.x = h0; ph.y = h1;
                    pl.x = __float2half_rn(v0 - __half2float(h0));
                    pl.y = __float2half_rn(v1 - __half2float(h1));
                    *(__half2*)(Ch + (long)b * sC + (long)row * Nc + col) = ph;
                    *(__half2*)(Cl + (long)b * sC + (long)row * Nc + col) = pl;
                } else {
                    float2 v; v.x = v0; v.y = v1;
                    *(float2*)(C + (long)b * sC + (long)row * Nc + col) = v;
                    const float2 t = *(const float2*)(text + (long)b * sT + (long)row * Nc + col);
                    float2 f; f.x = v.x + t.x; f.y = v.y + t.y;
                    *(float2*)(feat + (long)b * sT + (long)row * Nc + col) = f;
                }
            }
        }
    }
}

// ---------------- fp32 -> fp16 hi/lo split ----------------
__global__ void split_kernel(const float* __restrict__ s, __half* __restrict__ h,
                             __half* __restrict__ l, int n4)
{
    const int i = blockIdx.x * blockDim.x + threadIdx.x;
    if (i >= n4) return;
    const float4 v = ((const float4*)s)[i];
    union { uint2 u; __half q[4]; } ph, pl;
    #pragma unroll
    for (int q = 0; q < 4; ++q) {
        const float x = (&v.x)[q];
        const __half hh = __float2half_rn(x);
        ph.q[q] = hh;
        if (l) pl.q[q] = __float2half_rn(x - __half2float(hh));
    }
    ((uint2*)h)[i] = ph.u;
    if (l) ((uint2*)l)[i] = pl.u;
}

// ---------------- transpose + split: A[R,C] fp32 -> Th/Tl[C,R] fp16 ----------------
__global__ void tsplit_kernel(const float* __restrict__ A,
                              __half* __restrict__ Th, __half* __restrict__ Tl, int R, int C)
{
    __shared__ float t[32][33];
    const int r0 = blockIdx.x * 32, c0 = blockIdx.y * 32;
    #pragma unroll
    for (int r = threadIdx.y; r < 32; r += 8)
        t[r][threadIdx.x] = A[(size_t)(r0 + r) * C + c0 + threadIdx.x];
    __syncthreads();
    #pragma unroll
    for (int r = threadIdx.y; r < 32; r += 8) {
        const float v = t[threadIdx.x][r];
        const __half h = __float2half_rn(v);
        Th[(size_t)(c0 + r) * R + r0 + threadIdx.x] = h;
        Tl[(size_t)(c0 + r) * R + r0 + threadIdx.x] = __float2half_rn(v - __half2float(h));
    }
}

// ---------------- V transpose: V[b][n][d] fp32 -> Vt[b][d][n] fp16 (hi only) ----------------
__global__ void vtrans_kernel(const float* __restrict__ V, __half* __restrict__ Th)
{
    __shared__ float t[32][33];
    const int b = blockIdx.z;
    const float* Vb = V + (size_t)b * SEQ * DIM;
    const int n0 = blockIdx.x * 32, d0 = blockIdx.y * 32;
    #pragma unroll
    for (int r = threadIdx.y; r < 32; r += 8)
        t[r][threadIdx.x] = Vb[(size_t)(n0 + r) * DIM + d0 + threadIdx.x];
    __syncthreads();
    __half* Thb = Th + (size_t)b * DIM * SEQ;
    #pragma unroll
    for (int r = threadIdx.y; r < 32; r += 8)
        Thb[(size_t)(d0 + r) * SEQ + n0 + threadIdx.x] = __float2half_rn(t[threadIdx.x][r]);
}

// ---------------- softmax over QUERY axis (n of S[b][n][m]); writes fp16 alpha ----------------
__global__ void softmax_cols_kernel(const float* __restrict__ S, __half* __restrict__ Ah)
{
    const int b = blockIdx.y;
    const int m = blockIdx.x * blockDim.x + threadIdx.x;
    const float* Sb = S + (size_t)b * SEQ * SEQ;
    __half* Ahb = Ah + (size_t)b * SEQ * SEQ;

    float mx = -3.4e38f, s = 0.f;
    for (int n = 0; n < SEQ; ++n) {
        const float x = Sb[(size_t)n * SEQ + m];
        const float nm = fmaxf(mx, x);
        s = s * __expf(mx - nm) + __expf(x - nm);
        mx = nm;
    }
    const float inv = 1.f / s;
    for (int n = 0; n < SEQ; ++n) {
        const float x = Sb[(size_t)n * SEQ + m];
        Ahb[(size_t)n * SEQ + m] = __float2half_rn(__expf(x - mx) * inv);
    }
}

// ---------------- launch ----------------
extern "C" void kernel_launch(void* const* d_in, const int* in_sizes, int n_in,
                              void* d_out, int out_size)
{
    const float* img  = (const float*)d_in[0];
    const float* text = (const float*)d_in[1];
    const float* Wq   = (const float*)d_in[2];
    const float* Wk   = (const float*)d_in[3];
    const float* Wv   = (const float*)d_in[4];

    float* out  = (float*)d_out;
    float* feat = out + (size_t)MT * DIM;

    __half *imgh, *imgl, *texth, *textl, *wqth, *wqtl, *wkth, *wktl, *wvh;
    __half *gth, *gtl, *uh, *ul, *vth, *ah;
    float *v, *s;
    cudaGetSymbolAddress((void**)&imgh, g_img_h);   cudaGetSymbolAddress((void**)&imgl, g_img_l);
    cudaGetSymbolAddress((void**)&texth, g_text_h); cudaGetSymbolAddress((void**)&textl, g_text_l);
    cudaGetSymbolAddress((void**)&wqth, g_Wqt_h);   cudaGetSymbolAddress((void**)&wqtl, g_Wqt_l);
    cudaGetSymbolAddress((void**)&wkth, g_Wkt_h);   cudaGetSymbolAddress((void**)&wktl, g_Wkt_l);
    cudaGetSymbolAddress((void**)&wvh, g_Wv_h);
    cudaGetSymbolAddress((void**)&gth, g_Gt_h);     cudaGetSymbolAddress((void**)&gtl, g_Gt_l);
    cudaGetSymbolAddress((void**)&uh, g_U_h);       cudaGetSymbolAddress((void**)&ul, g_U_l);
    cudaGetSymbolAddress((void**)&v, g_V);
    cudaGetSymbolAddress((void**)&vth, g_Vth);
    cudaGetSymbolAddress((void**)&s, g_S);
    cudaGetSymbolAddress((void**)&ah, g_Ah);

    constexpr int SM22 = 3 * (2 * TILEB_A + 2 * TILEB_B);  // 184320
    constexpr int SM21 = 3 * (2 * TILEB_A + 1 * TILEB_B);  // 122880
    constexpr int SM11 = 3 * (1 * TILEB_A + 1 * TILEB_B);  // 92160
    cudaFuncSetAttribute(gemm_h<2,2,0>, cudaFuncAttributeMaxDynamicSharedMemorySize, SM22);
    cudaFuncSetAttribute(gemm_h<2,2,1>, cudaFuncAttributeMaxDynamicSharedMemorySize, SM22);
    cudaFuncSetAttribute(gemm_h<2,1,0>, cudaFuncAttributeMaxDynamicSharedMemorySize, SM21);
    cudaFuncSetAttribute(gemm_h<1,1,2>, cudaFuncAttributeMaxDynamicSharedMemorySize, SM11);

    const long nd = (long)SEQ * DIM;    // 2 M
    const long nn = (long)SEQ * SEQ;    // 4 M
    dim3 blk(256);

    // 1. split img/text; split Wv (hi only); transpose-split Wq, Wk
    {
        const int n4i = MT * DIM / 4;
        split_kernel<<<n4i / 256, 256>>>(img,  imgh,  imgl,  n4i);
        split_kernel<<<n4i / 256, 256>>>(text, texth, textl, n4i);
        const int n4w = DIM * DIM / 4;
        split_kernel<<<n4w / 256, 256>>>(Wv, wvh, nullptr, n4w);
        dim3 gt(DIM / 32, DIM / 32), bt(32, 8);
        tsplit_kernel<<<gt, bt>>>(Wq, wqth, wqtl, DIM, DIM);  // Wqt[d,i]
        tsplit_kernel<<<gt, bt>>>(Wk, wkth, wktl, DIM, DIM);  // Wkt[e,i]
    }

    // 2. Gt[e,d] = sum_i Wkt[e,i] * Wqt[d,i]   (3-term, split fp16 out)
    {
        dim3 g(DIM / 256, DIM / 128, 1);
        gemm_h<2,2,1><<<g, blk, SM22>>>(wkth, wktl, wqth, wqtl, DIM, DIM, DIM, 0, 0, 0,
                                        nullptr, gth, gtl, nullptr, nullptr, 0);
    }

    // 3. U[n,e] = sum_d img[n,d] * Gt[e,d]   (3-term, split fp16 out)
    //    V[n,i] = sum_e text[n,e] * Wv[i,e]  (2-term: text 2-limb x Wv hi)
    {
        dim3 g(DIM / 256, MT / 128, 1);
        gemm_h<2,2,1><<<g, blk, SM22>>>(imgh, imgl, gth, gtl, MT, DIM, DIM, 0, 0, 0,
                                        nullptr, uh, ul, nullptr, nullptr, 0);
        gemm_h<2,1,0><<<g, blk, SM21>>>(texth, textl, wvh, nullptr, MT, DIM, DIM, 0, 0, 0,
                                        v, nullptr, nullptr, nullptr, nullptr, 0);
    }

    // 4. transpose V (hi limb only)
    {
        dim3 g(SEQ / 32, DIM / 32, BB), bt(32, 8);
        vtrans_kernel<<<g, bt>>>(v, vth);
    }

    // 5. scores: per batch S[n,m] = sum_e U[n,e] * text[m,e]   (3-term)
    {
        dim3 g(SEQ / 256, SEQ / 128, BB);
        gemm_h<2,2,0><<<g, blk, SM22>>>(uh, ul, texth, textl, SEQ, SEQ, DIM, nd, nd, nn,
                                        s, nullptr, nullptr, nullptr, nullptr, 0);
    }

    // 6. softmax over query axis -> fp16 alpha
    {
        dim3 g(SEQ / 256, BB);
        softmax_cols_kernel<<<g, blk>>>(s, ah);
    }

    // 7. out = alpha_h @ Vt_h (1 term); feature = out + text
    {
        dim3 g(DIM / 256, SEQ / 128, BB);
        gemm_h<1,1,2><<<g, blk, SM11>>>(ah, nullptr, vth, nullptr, SEQ, DIM, SEQ, nn, nd, nd,
                                        out, nullptr, nullptr, text, feat, nd);
    }
}

// round 14
// speedup vs baseline: 3.3830x; 1.0224x over previous
#include <cuda_runtime.h>
#include <cuda_fp16.h>
#include <cstdint>

// ---------------- problem constants ----------------
#define BB   8
#define SEQ  2048
#define DIM  1024
#define MT   (BB * SEQ)          // 16384 flattened rows

// ---------------- PTX helpers (base-target legal, sm_80+) ----------------
__device__ __forceinline__ uint32_t smem_to_u32(const void* p) {
    uint32_t a;
    asm("{ .reg .u64 t; cvta.to.shared.u64 t, %1; cvt.u32.u64 %0, t; }" : "=r"(a) : "l"(p));
    return a;
}
#define CP_ASYNC16(dst, src) \
    asm volatile("cp.async.cg.shared.global [%0], [%1], 16;" :: "r"(dst), "l"(src))
#define CP_COMMIT() asm volatile("cp.async.commit_group;" ::: "memory")
#define CP_WAIT2()  asm volatile("cp.async.wait_group 2;" ::: "memory")
#define CP_WAIT1()  asm volatile("cp.async.wait_group 1;" ::: "memory")
#define CP_WAIT0()  asm volatile("cp.async.wait_group 0;" ::: "memory")

__device__ __forceinline__ void ldsm_x4(uint32_t* r, uint32_t addr) {
    asm volatile("ldmatrix.sync.aligned.m8n8.x4.shared.b16 {%0,%1,%2,%3}, [%4];"
                 : "=r"(r[0]), "=r"(r[1]), "=r"(r[2]), "=r"(r[3]) : "r"(addr));
}
__device__ __forceinline__ void mma16816(float* c, const uint32_t* a, const uint32_t* b) {
    asm volatile(
        "mma.sync.aligned.m16n8k16.row.col.f32.f16.f16.f32 "
        "{%0,%1,%2,%3}, {%4,%5,%6,%7}, {%8,%9}, {%0,%1,%2,%3};"
        : "+f"(c[0]), "+f"(c[1]), "+f"(c[2]), "+f"(c[3])
        : "r"(a[0]), "r"(a[1]), "r"(a[2]), "r"(a[3]), "r"(b[0]), "r"(b[1]));
}

// ---------------- scratch (no cudaMalloc allowed) ----------------
__device__ __half g_img_h[(size_t)MT * DIM], g_img_l[(size_t)MT * DIM];
__device__ __half g_text_h[(size_t)MT * DIM], g_text_l[(size_t)MT * DIM];
__device__ __half g_Wqt_h[(size_t)DIM * DIM], g_Wqt_l[(size_t)DIM * DIM];   // Wq^T [d,i]
__device__ __half g_Wkt_h[(size_t)DIM * DIM], g_Wkt_l[(size_t)DIM * DIM];   // Wk^T [e,i]
__device__ __half g_Wv_h[(size_t)DIM * DIM];
__device__ __half g_Gt_h[(size_t)DIM * DIM], g_Gt_l[(size_t)DIM * DIM];     // G^T [e,d]
__device__ float  g_P[(size_t)8 * DIM * DIM];                                // split-K partials
__device__ __half g_U_h[(size_t)MT * DIM], g_U_l[(size_t)MT * DIM];         // img @ G
__device__ float  g_V[(size_t)MT * DIM];
__device__ __half g_Vth[(size_t)MT * DIM];                                   // [B][DIM][SEQ]
__device__ float  g_S[(size_t)BB * SEQ * SEQ];
__device__ __half g_Ah[(size_t)BB * SEQ * SEQ];

// ---------------- GEMM: C[M,Nc] ~= (A0[+A1]) @ (B0[+B1])^T, fp16 HMMA ----------------
// Terms: A0B0 always; A0B1 if TB==2; A1B0 if TA==2 (A1B1 dropped).
// BM=128, BN=128*NH, BK=32, 3-stage cp.async, warp tile 64 x 32*NH (8 warps 2x4).
// SMEM rows 80B (64B data + 16 pad) -> conflict-free ldmatrix & cp.async.
// SK=1: blockIdx.z = K-chunk (offset z*Klen into K of A and B; C += z*sC as partial).
#define ROWB     80
#define TILEB_A  (128 * ROWB)            // 10240

template<int TA, int TB, int EPI, int NH, int SK>
// EPI 0: fp32 C   1: split fp16 Ch/Cl   2: fp32 C + feat=C+text
__global__ void __launch_bounds__(256, 1)
gemm_h(const __half* __restrict__ A0, const __half* __restrict__ A1,
       const __half* __restrict__ B0, const __half* __restrict__ B1,
       int M, int Nc, int Kd, int Klen, long sA, long sB, long sC,
       float* __restrict__ C, __half* __restrict__ Ch, __half* __restrict__ Cl,
       const float* __restrict__ text, float* __restrict__ feat, long sT)
{
    constexpr uint32_t TILEB_B = (uint32_t)(128 * NH * ROWB);
    constexpr uint32_t T_A0 = 0;
    constexpr uint32_t T_A1 = TILEB_A;                 // valid iff TA==2
    constexpr uint32_t T_B0 = TA * TILEB_A;
    constexpr uint32_t T_B1 = T_B0 + TILEB_B;          // valid iff TB==2
    constexpr uint32_t STAGE_SZ = TA * TILEB_A + TB * TILEB_B;

    extern __shared__ char smem[];
    const uint32_t sbase = smem_to_u32(smem);
    const int tid = threadIdx.x;
    const int wid = tid >> 5;
    const int lid = tid & 31;
    const int b = blockIdx.z;

    const int mBase = blockIdx.y * 128;
    const int nBase = blockIdx.x * (128 * NH);

    const long aoff = SK ? (long)b * Klen : (long)b * sA;
    const long boff = SK ? (long)b * Klen : (long)b * sB;
    const __half* gA0 = A0 + aoff + (long)mBase * Kd;
    const __half* gA1 = (TA == 2) ? A1 + aoff + (long)mBase * Kd : nullptr;
    const __half* gB0 = B0 + boff + (long)nBase * Kd;
    const __half* gB1 = (TB == 2) ? B1 + boff + (long)nBase * Kd : nullptr;

    auto load_stage = [&](int k0, int s) {
        const uint32_t st = sbase + (uint32_t)s * STAGE_SZ;
        #pragma unroll
        for (int c = 0; c < 2; ++c) {          // A: 512 16B chunks per tile
            const int ch = tid + c * 256;
            const int r = ch >> 2, col = (ch & 3) * 16;
            CP_ASYNC16(st + T_A0 + r * ROWB + col, (const char*)(gA0 + (long)r * Kd + k0) + col);
            if (TA == 2)
                CP_ASYNC16(st + T_A1 + r * ROWB + col, (const char*)(gA1 + (long)r * Kd + k0) + col);
        }
        #pragma unroll
        for (int c = 0; c < 2 * NH; ++c) {     // B: 512*NH chunks per tile
            const int ch = tid + c * 256;
            const int r = ch >> 2, col = (ch & 3) * 16;
            CP_ASYNC16(st + T_B0 + r * ROWB + col, (const char*)(gB0 + (long)r * Kd + k0) + col);
            if (TB == 2)
                CP_ASYNC16(st + T_B1 + r * ROWB + col, (const char*)(gB1 + (long)r * Kd + k0) + col);
        }
    };

    const int wm = (wid >> 2) * 64;
    const int wn = (wid & 3) * (32 * NH);

    const uint32_t aOff = (uint32_t)((lid & 15) * ROWB + (lid >> 4) * 16);
    const uint32_t bOff = (uint32_t)((((lid >> 4) << 3) + (lid & 7)) * ROWB + ((lid >> 3) & 1) * 16);

    float acc[4][4 * NH][4];
    #pragma unroll
    for (int mi = 0; mi < 4; ++mi)
        #pragma unroll
        for (int ni = 0; ni < 4 * NH; ++ni)
            #pragma unroll
            for (int q = 0; q < 4; ++q) acc[mi][ni][q] = 0.f;

    const int nch = Klen >> 5;

    load_stage(0, 0);  CP_COMMIT();
    load_stage(32, 1); CP_COMMIT();

    int cur = 0, nxt = 2;
    for (int i = 0; i < nch; ++i) {
        if (i + 2 < nch)      { load_stage((i + 2) << 5, nxt); CP_COMMIT(); CP_WAIT2(); }
        else if (i + 1 < nch) { CP_WAIT1(); }
        else                  { CP_WAIT0(); }
        __syncthreads();

        const uint32_t st = sbase + (uint32_t)cur * STAGE_SZ;
        const uint32_t aBase = st + (uint32_t)(wm * ROWB);
        const uint32_t bBase = st + (uint32_t)(wn * ROWB);

        #pragma unroll
        for (int kk = 0; kk < 2; ++kk) {
            const uint32_t kb = kk * 32;
            uint32_t a0r[4][4], a1r[4][4];
            #pragma unroll
            for (int mi = 0; mi < 4; ++mi) {
                ldsm_x4(a0r[mi], aBase + T_A0 + (uint32_t)(mi * 16 * ROWB) + aOff + kb);
                if (TA == 2)
                    ldsm_x4(a1r[mi], aBase + T_A1 + (uint32_t)(mi * 16 * ROWB) + aOff + kb);
            }
            #pragma unroll
            for (int nh = 0; nh < NH; ++nh) {
                uint32_t b0r[8], b1r[8];
                #pragma unroll
                for (int nb = 0; nb < 2; ++nb) {
                    const uint32_t nrow = (uint32_t)((nh * 32 + nb * 16) * ROWB);
                    ldsm_x4(&b0r[nb * 4], bBase + T_B0 + nrow + bOff + kb);
                    if (TB == 2)
                        ldsm_x4(&b1r[nb * 4], bBase + T_B1 + nrow + bOff + kb);
                }
                #pragma unroll
                for (int mi = 0; mi < 4; ++mi)
                    #pragma unroll
                    for (int nj = 0; nj < 4; ++nj) {
                        float* a4 = acc[mi][nh * 4 + nj];
                        mma16816(a4, a0r[mi], &b0r[nj * 2]);
                        if (TB == 2) mma16816(a4, a0r[mi], &b1r[nj * 2]);
                        if (TA == 2) mma16816(a4, a1r[mi], &b0r[nj * 2]);
                    }
            }
        }
        __syncthreads();
        cur = (cur == 2) ? 0 : cur + 1;
        nxt = (nxt == 2) ? 0 : nxt + 1;
    }

    // ---- epilogue ----
    const int rowA = mBase + wm + (lid >> 2);
    const int colA = nBase + wn + (lid & 3) * 2;
    #pragma unroll
    for (int mi = 0; mi < 4; ++mi) {
        #pragma unroll
        for (int half = 0; half < 2; ++half) {
            const int row = rowA + mi * 16 + half * 8;
            #pragma unroll
            for (int ni = 0; ni < 4 * NH; ++ni) {
                const int col = colA + ni * 8;
                const float v0 = acc[mi][ni][half * 2 + 0];
                const float v1 = acc[mi][ni][half * 2 + 1];
                if (EPI == 0) {
                    float2 v; v.x = v0; v.y = v1;
                    *(float2*)(C + (long)b * sC + (long)row * Nc + col) = v;
                } else if (EPI == 1) {
                    const __half h0 = __float2half_rn(v0);
                    const __half h1 = __float2half_rn(v1);
                    __half2 ph, pl;
                    ph.x = h0; ph.y = h1;
                    pl.x = __float2half_rn(v0 - __half2float(h0));
                    pl.y = __float2half_rn(v1 - __half2float(h1));
                    *(__half2*)(Ch + (long)b * sC + (long)row * Nc + col) = ph;
                    *(__half2*)(Cl + (long)b * sC + (long)row * Nc + col) = pl;
                } else {
                    float2 v; v.x = v0; v.y = v1;
                    *(float2*)(C + (long)b * sC + (long)row * Nc + col) = v;
                    const float2 t = *(const float2*)(text + (long)b * sT + (long)row * Nc + col);
                    float2 f; f.x = v.x + t.x; f.y = v.y + t.y;
                    *(float2*)(feat + (long)b * sT + (long)row * Nc + col) = f;
                }
            }
        }
    }
}

// ---------------- split-K reduce + fp16 hi/lo split ----------------
__global__ void reduce_split_kernel(const float* __restrict__ P,
                                    __half* __restrict__ h, __half* __restrict__ l, int n4)
{
    const int i = blockIdx.x * blockDim.x + threadIdx.x;
    if (i >= n4) return;
    float4 s = ((const float4*)P)[i];
    #pragma unroll
    for (int p = 1; p < 8; ++p) {
        const float4 v = ((const float4*)P)[(size_t)p * (DIM * (size_t)DIM / 4) + i];
        s.x += v.x; s.y += v.y; s.z += v.z; s.w += v.w;
    }
    union { uint2 u; __half q[4]; } ph, pl;
    #pragma unroll
    for (int q = 0; q < 4; ++q) {
        const float x = (&s.x)[q];
        const __half hh = __float2half_rn(x);
        ph.q[q] = hh;
        pl.q[q] = __float2half_rn(x - __half2float(hh));
    }
    ((uint2*)h)[i] = ph.u;
    ((uint2*)l)[i] = pl.u;
}

// ---------------- fp32 -> fp16 hi/lo split ----------------
__global__ void split_kernel(const float* __restrict__ s, __half* __restrict__ h,
                             __half* __restrict__ l, int n4)
{
    const int i = blockIdx.x * blockDim.x + threadIdx.x;
    if (i >= n4) return;
    const float4 v = ((const float4*)s)[i];
    union { uint2 u; __half q[4]; } ph, pl;
    #pragma unroll
    for (int q = 0; q < 4; ++q) {
        const float x = (&v.x)[q];
        const __half hh = __float2half_rn(x);
        ph.q[q] = hh;
        if (l) pl.q[q] = __float2half_rn(x - __half2float(hh));
    }
    ((uint2*)h)[i] = ph.u;
    if (l) ((uint2*)l)[i] = pl.u;
}

// ---------------- transpose + split: A[R,C] fp32 -> Th/Tl[C,R] fp16 ----------------
__global__ void tsplit_kernel(const float* __restrict__ A,
                              __half* __restrict__ Th, __half* __restrict__ Tl, int R, int C)
{
    __shared__ float t[32][33];
    const int r0 = blockIdx.x * 32, c0 = blockIdx.y * 32;
    #pragma unroll
    for (int r = threadIdx.y; r < 32; r += 8)
        t[r][threadIdx.x] = A[(size_t)(r0 + r) * C + c0 + threadIdx.x];
    __syncthreads();
    #pragma unroll
    for (int r = threadIdx.y; r < 32; r += 8) {
        const float v = t[threadIdx.x][r];
        const __half h = __float2half_rn(v);
        Th[(size_t)(c0 + r) * R + r0 + threadIdx.x] = h;
        Tl[(size_t)(c0 + r) * R + r0 + threadIdx.x] = __float2half_rn(v - __half2float(h));
    }
}

// ---------------- V transpose: V[b][n][d] fp32 -> Vt[b][d][n] fp16 (hi only) ----------------
__global__ void vtrans_kernel(const float* __restrict__ V, __half* __restrict__ Th)
{
    __shared__ float t[32][33];
    const int b = blockIdx.z;
    const float* Vb = V + (size_t)b * SEQ * DIM;
    const int n0 = blockIdx.x * 32, d0 = blockIdx.y * 32;
    #pragma unroll
    for (int r = threadIdx.y; r < 32; r += 8)
        t[r][threadIdx.x] = Vb[(size_t)(n0 + r) * DIM + d0 + threadIdx.x];
    __syncthreads();
    __half* Thb = Th + (size_t)b * DIM * SEQ;
    #pragma unroll
    for (int r = threadIdx.y; r < 32; r += 8)
        Thb[(size_t)(d0 + r) * SEQ + n0 + threadIdx.x] = __float2half_rn(t[threadIdx.x][r]);
}

// ---------------- softmax over QUERY axis (n of S[b][n][m]); writes fp16 alpha ----------------
__global__ void softmax_cols_kernel(const float* __restrict__ S, __half* __restrict__ Ah)
{
    const int b = blockIdx.y;
    const int m = blockIdx.x * blockDim.x + threadIdx.x;
    const float* Sb = S + (size_t)b * SEQ * SEQ;
    __half* Ahb = Ah + (size_t)b * SEQ * SEQ;

    float mx = -3.4e38f, s = 0.f;
    for (int n = 0; n < SEQ; ++n) {
        const float x = Sb[(size_t)n * SEQ + m];
        const float nm = fmaxf(mx, x);
        s = s * __expf(mx - nm) + __expf(x - nm);
        mx = nm;
    }
    const float inv = 1.f / s;
    for (int n = 0; n < SEQ; ++n) {
        const float x = Sb[(size_t)n * SEQ + m];
        Ahb[(size_t)n * SEQ + m] = __float2half_rn(__expf(x - mx) * inv);
    }
}

// ---------------- launch ----------------
extern "C" void kernel_launch(void* const* d_in, const int* in_sizes, int n_in,
                              void* d_out, int out_size)
{
    const float* img  = (const float*)d_in[0];
    const float* text = (const float*)d_in[1];
    const float* Wq   = (const float*)d_in[2];
    const float* Wk   = (const float*)d_in[3];
    const float* Wv   = (const float*)d_in[4];

    float* out  = (float*)d_out;
    float* feat = out + (size_t)MT * DIM;

    __half *imgh, *imgl, *texth, *textl, *wqth, *wqtl, *wkth, *wktl, *wvh;
    __half *gth, *gtl, *uh, *ul, *vth, *ah;
    float *v, *s, *p;
    cudaGetSymbolAddress((void**)&imgh, g_img_h);   cudaGetSymbolAddress((void**)&imgl, g_img_l);
    cudaGetSymbolAddress((void**)&texth, g_text_h); cudaGetSymbolAddress((void**)&textl, g_text_l);
    cudaGetSymbolAddress((void**)&wqth, g_Wqt_h);   cudaGetSymbolAddress((void**)&wqtl, g_Wqt_l);
    cudaGetSymbolAddress((void**)&wkth, g_Wkt_h);   cudaGetSymbolAddress((void**)&wktl, g_Wkt_l);
    cudaGetSymbolAddress((void**)&wvh, g_Wv_h);
    cudaGetSymbolAddress((void**)&gth, g_Gt_h);     cudaGetSymbolAddress((void**)&gtl, g_Gt_l);
    cudaGetSymbolAddress((void**)&p, g_P);
    cudaGetSymbolAddress((void**)&uh, g_U_h);       cudaGetSymbolAddress((void**)&ul, g_U_l);
    cudaGetSymbolAddress((void**)&v, g_V);
    cudaGetSymbolAddress((void**)&vth, g_Vth);
    cudaGetSymbolAddress((void**)&s, g_S);
    cudaGetSymbolAddress((void**)&ah, g_Ah);

    // smem sizes per instantiation (3 stages)
    constexpr int SM_GT = 3 * (2 * TILEB_A + 2 * TILEB_A);      // 122880  <2,2,0,1,1>
    constexpr int SM_U  = 3 * (2 * TILEB_A + 2 * TILEB_A);      // 122880  <2,2,1,1,0>
    constexpr int SM_VP = 3 * (2 * TILEB_A + 1 * TILEB_A);      // 92160   <2,1,0,1,0>
    constexpr int SM_S  = 3 * (2 * TILEB_A + 2 * 2 * TILEB_A);  // 184320  <2,2,0,2,0>
    constexpr int SM_AV = 3 * (1 * TILEB_A + 1 * TILEB_A);      // 61440   <1,1,2,1,0>
    cudaFuncSetAttribute(gemm_h<2,2,0,1,1>, cudaFuncAttributeMaxDynamicSharedMemorySize, SM_GT);
    cudaFuncSetAttribute(gemm_h<2,2,1,1,0>, cudaFuncAttributeMaxDynamicSharedMemorySize, SM_U);
    cudaFuncSetAttribute(gemm_h<2,1,0,1,0>, cudaFuncAttributeMaxDynamicSharedMemorySize, SM_VP);
    cudaFuncSetAttribute(gemm_h<2,2,0,2,0>, cudaFuncAttributeMaxDynamicSharedMemorySize, SM_S);
    cudaFuncSetAttribute(gemm_h<1,1,2,1,0>, cudaFuncAttributeMaxDynamicSharedMemorySize, SM_AV);

    const long nd = (long)SEQ * DIM;    // 2 M
    const long nn = (long)SEQ * SEQ;    // 4 M
    dim3 blk(256);

    // 1. split img/text; split Wv (hi only); transpose-split Wq, Wk
    {
        const int n4i = MT * DIM / 4;
        split_kernel<<<n4i / 256, 256>>>(img,  imgh,  imgl,  n4i);
        split_kernel<<<n4i / 256, 256>>>(text, texth, textl, n4i);
        const int n4w = DIM * DIM / 4;
        split_kernel<<<n4w / 256, 256>>>(Wv, wvh, nullptr, n4w);
        dim3 gt(DIM / 32, DIM / 32), bt(32, 8);
        tsplit_kernel<<<gt, bt>>>(Wq, wqth, wqtl, DIM, DIM);  // Wqt[d,i]
        tsplit_kernel<<<gt, bt>>>(Wk, wkth, wktl, DIM, DIM);  // Wkt[e,i]
    }

    // 2. Gt[e,d] = sum_i Wkt[e,i] * Wqt[d,i]  — split-K x8 partials, then reduce+split
    {
        dim3 g(DIM / 128, DIM / 128, 8);
        gemm_h<2,2,0,1,1><<<g, blk, SM_GT>>>(wkth, wktl, wqth, wqtl, DIM, DIM, DIM, DIM / 8,
                                             0, 0, (long)DIM * DIM,
                                             p, nullptr, nullptr, nullptr, nullptr, 0);
        const int n4g = DIM * DIM / 4;
        reduce_split_kernel<<<n4g / 256, 256>>>(p, gth, gtl, n4g);
    }

    // 3. U[n,e] = sum_d img[n,d] * Gt[e,d]   (3-term, split fp16 out)
    //    V[n,i] = sum_e text[n,e] * Wv[i,e]  (2-term: text 2-limb x Wv hi)
    {
        dim3 g(DIM / 128, MT / 128, 1);
        gemm_h<2,2,1,1,0><<<g, blk, SM_U>>>(imgh, imgl, gth, gtl, MT, DIM, DIM, DIM, 0, 0, 0,
                                            nullptr, uh, ul, nullptr, nullptr, 0);
        gemm_h<2,1,0,1,0><<<g, blk, SM_VP>>>(texth, textl, wvh, nullptr, MT, DIM, DIM, DIM, 0, 0, 0,
                                             v, nullptr, nullptr, nullptr, nullptr, 0);
    }

    // 4. transpose V (hi limb only)
    {
        dim3 g(SEQ / 32, DIM / 32, BB), bt(32, 8);
        vtrans_kernel<<<g, bt>>>(v, vth);
    }

    // 5. scores: per batch S[n,m] = sum_e U[n,e] * text[m,e]   (3-term, BN=256)
    {
        dim3 g(SEQ / 256, SEQ / 128, BB);
        gemm_h<2,2,0,2,0><<<g, blk, SM_S>>>(uh, ul, texth, textl, SEQ, SEQ, DIM, DIM, nd, nd, nn,
                                            s, nullptr, nullptr, nullptr, nullptr, 0);
    }

    // 6. softmax over query axis -> fp16 alpha
    {
        dim3 g(SEQ / 256, BB);
        softmax_cols_kernel<<<g, blk>>>(s, ah);
    }

    // 7. out = alpha_h @ Vt_h (1 term, BN=128); feature = out + text
    {
        dim3 g(DIM / 128, SEQ / 128, BB);
        gemm_h<1,1,2,1,0><<<g, blk, SM_AV>>>(ah, nullptr, vth, nullptr, SEQ, DIM, SEQ, SEQ, nn, nd, nd,
                                             out, nullptr, nullptr, text, feat, nd);
    }
}

// round 16
// speedup vs baseline: 3.5459x; 1.0481x over previous
#include <cuda_runtime.h>
#include <cuda_fp16.h>
#include <cstdint>

// ---------------- problem constants ----------------
#define BB   8
#define SEQ  2048
#define DIM  1024
#define MT   (BB * SEQ)          // 16384 flattened rows

// ---------------- PTX helpers (base-target legal, sm_80+) ----------------
__device__ __forceinline__ uint32_t smem_to_u32(const void* p) {
    uint32_t a;
    asm("{ .reg .u64 t; cvta.to.shared.u64 t, %1; cvt.u32.u64 %0, t; }" : "=r"(a) : "l"(p));
    return a;
}
#define CP_ASYNC16(dst, src) \
    asm volatile("cp.async.cg.shared.global [%0], [%1], 16;" :: "r"(dst), "l"(src))
#define CP_COMMIT() asm volatile("cp.async.commit_group;" ::: "memory")
#define CP_WAIT2()  asm volatile("cp.async.wait_group 2;" ::: "memory")
#define CP_WAIT1()  asm volatile("cp.async.wait_group 1;" ::: "memory")
#define CP_WAIT0()  asm volatile("cp.async.wait_group 0;" ::: "memory")

__device__ __forceinline__ void ldsm_x4(uint32_t* r, uint32_t addr) {
    asm volatile("ldmatrix.sync.aligned.m8n8.x4.shared.b16 {%0,%1,%2,%3}, [%4];"
                 : "=r"(r[0]), "=r"(r[1]), "=r"(r[2]), "=r"(r[3]) : "r"(addr));
}
__device__ __forceinline__ void mma16816(float* c, const uint32_t* a, const uint32_t* b) {
    asm volatile(
        "mma.sync.aligned.m16n8k16.row.col.f32.f16.f16.f32 "
        "{%0,%1,%2,%3}, {%4,%5,%6,%7}, {%8,%9}, {%0,%1,%2,%3};"
        : "+f"(c[0]), "+f"(c[1]), "+f"(c[2]), "+f"(c[3])
        : "r"(a[0]), "r"(a[1]), "r"(a[2]), "r"(a[3]), "r"(b[0]), "r"(b[1]));
}

// ---------------- scratch (no cudaMalloc allowed) ----------------
__device__ __half g_img_h[(size_t)MT * DIM], g_img_l[(size_t)MT * DIM];
__device__ __half g_text_h[(size_t)MT * DIM], g_text_l[(size_t)MT * DIM];
__device__ __half g_Wqt_h[(size_t)DIM * DIM], g_Wqt_l[(size_t)DIM * DIM];   // Wq^T [d,i]
__device__ __half g_Wkt_h[(size_t)DIM * DIM], g_Wkt_l[(size_t)DIM * DIM];   // Wk^T [e,i]
__device__ __half g_Wv_h[(size_t)DIM * DIM];
__device__ __half g_Gt_h[(size_t)DIM * DIM], g_Gt_l[(size_t)DIM * DIM];     // G^T [e,d]
__device__ float  g_P[(size_t)8 * DIM * DIM];                                // split-K partials
__device__ __half g_U_h[(size_t)MT * DIM], g_U_l[(size_t)MT * DIM];         // img @ G
__device__ float  g_V[(size_t)MT * DIM];
__device__ __half g_Vth[(size_t)MT * DIM];                                   // [B][DIM][SEQ]
__device__ float  g_S[(size_t)BB * SEQ * SEQ];
__device__ __half g_Ah[(size_t)BB * SEQ * SEQ];

// ---------------- GEMM: C[M,Nc] ~= (A0[+A1]) @ (B0[+B1])^T, fp16 HMMA ----------------
// Terms: A0B0 always; A0B1 if TB==2; A1B0 if TA==2 (A1B1 dropped).
// BM=128, BN=128*NH, BK=32, 3-stage cp.async, warp tile 64 x 32*NH (8 warps 2x4).
// SMEM rows 80B (64B data + 16 pad) -> conflict-free ldmatrix & cp.async.
// SK=1: blockIdx.z = K-chunk (offset z*Klen into K of A and B; C += z*sC as partial).
#define ROWB     80
#define TILEB_A  (128 * ROWB)            // 10240

template<int TA, int TB, int EPI, int NH, int SK>
// EPI 0: fp32 C   1: split fp16 Ch/Cl   2: fp32 C + feat=C+text
__global__ void __launch_bounds__(256, 1)
gemm_h(const __half* __restrict__ A0, const __half* __restrict__ A1,
       const __half* __restrict__ B0, const __half* __restrict__ B1,
       int M, int Nc, int Kd, int Klen, long sA, long sB, long sC,
       float* __restrict__ C, __half* __restrict__ Ch, __half* __restrict__ Cl,
       const float* __restrict__ text, float* __restrict__ feat, long sT)
{
    constexpr uint32_t TILEB_B = (uint32_t)(128 * NH * ROWB);
    constexpr uint32_t T_A0 = 0;
    constexpr uint32_t T_A1 = TILEB_A;                 // valid iff TA==2
    constexpr uint32_t T_B0 = TA * TILEB_A;
    constexpr uint32_t T_B1 = T_B0 + TILEB_B;          // valid iff TB==2
    constexpr uint32_t STAGE_SZ = TA * TILEB_A + TB * TILEB_B;

    extern __shared__ char smem[];
    const uint32_t sbase = smem_to_u32(smem);
    const int tid = threadIdx.x;
    const int wid = tid >> 5;
    const int lid = tid & 31;
    const int b = blockIdx.z;

    const int mBase = blockIdx.y * 128;
    const int nBase = blockIdx.x * (128 * NH);

    const long aoff = SK ? (long)b * Klen : (long)b * sA;
    const long boff = SK ? (long)b * Klen : (long)b * sB;
    const __half* gA0 = A0 + aoff + (long)mBase * Kd;
    const __half* gA1 = (TA == 2) ? A1 + aoff + (long)mBase * Kd : nullptr;
    const __half* gB0 = B0 + boff + (long)nBase * Kd;
    const __half* gB1 = (TB == 2) ? B1 + boff + (long)nBase * Kd : nullptr;

    auto load_stage = [&](int k0, int s) {
        const uint32_t st = sbase + (uint32_t)s * STAGE_SZ;
        #pragma unroll
        for (int c = 0; c < 2; ++c) {          // A: 512 16B chunks per tile
            const int ch = tid + c * 256;
            const int r = ch >> 2, col = (ch & 3) * 16;
            CP_ASYNC16(st + T_A0 + r * ROWB + col, (const char*)(gA0 + (long)r * Kd + k0) + col);
            if (TA == 2)
                CP_ASYNC16(st + T_A1 + r * ROWB + col, (const char*)(gA1 + (long)r * Kd + k0) + col);
        }
        #pragma unroll
        for (int c = 0; c < 2 * NH; ++c) {     // B: 512*NH chunks per tile
            const int ch = tid + c * 256;
            const int r = ch >> 2, col = (ch & 3) * 16;
            CP_ASYNC16(st + T_B0 + r * ROWB + col, (const char*)(gB0 + (long)r * Kd + k0) + col);
            if (TB == 2)
                CP_ASYNC16(st + T_B1 + r * ROWB + col, (const char*)(gB1 + (long)r * Kd + k0) + col);
        }
    };

    const int wm = (wid >> 2) * 64;
    const int wn = (wid & 3) * (32 * NH);

    const uint32_t aOff = (uint32_t)((lid & 15) * ROWB + (lid >> 4) * 16);
    const uint32_t bOff = (uint32_t)((((lid >> 4) << 3) + (lid & 7)) * ROWB + ((lid >> 3) & 1) * 16);

    float acc[4][4 * NH][4];
    #pragma unroll
    for (int mi = 0; mi < 4; ++mi)
        #pragma unroll
        for (int ni = 0; ni < 4 * NH; ++ni)
            #pragma unroll
            for (int q = 0; q < 4; ++q) acc[mi][ni][q] = 0.f;

    const int nch = Klen >> 5;

    load_stage(0, 0);  CP_COMMIT();
    load_stage(32, 1); CP_COMMIT();

    int cur = 0, nxt = 2;
    for (int i = 0; i < nch; ++i) {
        if (i + 2 < nch)      { load_stage((i + 2) << 5, nxt); CP_COMMIT(); CP_WAIT2(); }
        else if (i + 1 < nch) { CP_WAIT1(); }
        else                  { CP_WAIT0(); }
        __syncthreads();

        const uint32_t st = sbase + (uint32_t)cur * STAGE_SZ;
        const uint32_t aBase = st + (uint32_t)(wm * ROWB);
        const uint32_t bBase = st + (uint32_t)(wn * ROWB);

        #pragma unroll
        for (int kk = 0; kk < 2; ++kk) {
            const uint32_t kb = kk * 32;
            uint32_t a0r[4][4], a1r[4][4];
            #pragma unroll
            for (int mi = 0; mi < 4; ++mi) {
                ldsm_x4(a0r[mi], aBase + T_A0 + (uint32_t)(mi * 16 * ROWB) + aOff + kb);
                if (TA == 2)
                    ldsm_x4(a1r[mi], aBase + T_A1 + (uint32_t)(mi * 16 * ROWB) + aOff + kb);
            }
            #pragma unroll
            for (int nh = 0; nh < NH; ++nh) {
                uint32_t b0r[8], b1r[8];
                #pragma unroll
                for (int nb = 0; nb < 2; ++nb) {
                    const uint32_t nrow = (uint32_t)((nh * 32 + nb * 16) * ROWB);
                    ldsm_x4(&b0r[nb * 4], bBase + T_B0 + nrow + bOff + kb);
                    if (TB == 2)
                        ldsm_x4(&b1r[nb * 4], bBase + T_B1 + nrow + bOff + kb);
                }
                #pragma unroll
                for (int mi = 0; mi < 4; ++mi)
                    #pragma unroll
                    for (int nj = 0; nj < 4; ++nj) {
                        float* a4 = acc[mi][nh * 4 + nj];
                        mma16816(a4, a0r[mi], &b0r[nj * 2]);
                        if (TB == 2) mma16816(a4, a0r[mi], &b1r[nj * 2]);
                        if (TA == 2) mma16816(a4, a1r[mi], &b0r[nj * 2]);
                    }
            }
        }
        __syncthreads();
        cur = (cur == 2) ? 0 : cur + 1;
        nxt = (nxt == 2) ? 0 : nxt + 1;
    }

    // ---- epilogue ----
    const int rowA = mBase + wm + (lid >> 2);
    const int colA = nBase + wn + (lid & 3) * 2;
    #pragma unroll
    for (int mi = 0; mi < 4; ++mi) {
        #pragma unroll
        for (int half = 0; half < 2; ++half) {
            const int row = rowA + mi * 16 + half * 8;
            #pragma unroll
            for (int ni = 0; ni < 4 * NH; ++ni) {
                const int col = colA + ni * 8;
                const float v0 = acc[mi][ni][half * 2 + 0];
                const float v1 = acc[mi][ni][half * 2 + 1];
                if (EPI == 0) {
                    float2 v; v.x = v0; v.y = v1;
                    *(float2*)(C + (long)b * sC + (long)row * Nc + col) = v;
                } else if (EPI == 1) {
                    const __half h0 = __float2half_rn(v0);
                    const __half h1 = __float2half_rn(v1);
                    __half2 ph, pl;
                    ph.x = h0; ph.y = h1;
                    pl.x = __float2half_rn(v0 - __half2float(h0));
                    pl.y = __float2half_rn(v1 - __half2float(h1));
                    *(__half2*)(Ch + (long)b * sC + (long)row * Nc + col) = ph;
                    *(__half2*)(Cl + (long)b * sC + (long)row * Nc + col) = pl;
                } else {
                    float2 v; v.x = v0; v.y = v1;
                    *(float2*)(C + (long)b * sC + (long)row * Nc + col) = v;
                    const float2 t = *(const float2*)(text + (long)b * sT + (long)row * Nc + col);
                    float2 f; f.x = v.x + t.x; f.y = v.y + t.y;
                    *(float2*)(feat + (long)b * sT + (long)row * Nc + col) = f;
                }
            }
        }
    }
}

// ---------------- split-K reduce + fp16 hi/lo split ----------------
__global__ void reduce_split_kernel(const float* __restrict__ P,
                                    __half* __restrict__ h, __half* __restrict__ l, int n4)
{
    const int i = blockIdx.x * blockDim.x + threadIdx.x;
    if (i >= n4) return;
    float4 s = ((const float4*)P)[i];
    #pragma unroll
    for (int p = 1; p < 8; ++p) {
        const float4 v = ((const float4*)P)[(size_t)p * (DIM * (size_t)DIM / 4) + i];
        s.x += v.x; s.y += v.y; s.z += v.z; s.w += v.w;
    }
    union { uint2 u; __half q[4]; } ph, pl;
    #pragma unroll
    for (int q = 0; q < 4; ++q) {
        const float x = (&s.x)[q];
        const __half hh = __float2half_rn(x);
        ph.q[q] = hh;
        pl.q[q] = __float2half_rn(x - __half2float(hh));
    }
    ((uint2*)h)[i] = ph.u;
    ((uint2*)l)[i] = pl.u;
}

// ---------------- fp32 -> fp16 hi/lo split ----------------
__global__ void split_kernel(const float* __restrict__ s, __half* __restrict__ h,
                             __half* __restrict__ l, int n4)
{
    const int i = blockIdx.x * blockDim.x + threadIdx.x;
    if (i >= n4) return;
    const float4 v = ((const float4*)s)[i];
    union { uint2 u; __half q[4]; } ph, pl;
    #pragma unroll
    for (int q = 0; q < 4; ++q) {
        const float x = (&v.x)[q];
        const __half hh = __float2half_rn(x);
        ph.q[q] = hh;
        if (l) pl.q[q] = __float2half_rn(x - __half2float(hh));
    }
    ((uint2*)h)[i] = ph.u;
    if (l) ((uint2*)l)[i] = pl.u;
}

// ---------------- transpose + split: A[R,C] fp32 -> Th/Tl[C,R] fp16 ----------------
__global__ void tsplit_kernel(const float* __restrict__ A,
                              __half* __restrict__ Th, __half* __restrict__ Tl, int R, int C)
{
    __shared__ float t[32][33];
    const int r0 = blockIdx.x * 32, c0 = blockIdx.y * 32;
    #pragma unroll
    for (int r = threadIdx.y; r < 32; r += 8)
        t[r][threadIdx.x] = A[(size_t)(r0 + r) * C + c0 + threadIdx.x];
    __syncthreads();
    #pragma unroll
    for (int r = threadIdx.y; r < 32; r += 8) {
        const float v = t[threadIdx.x][r];
        const __half h = __float2half_rn(v);
        Th[(size_t)(c0 + r) * R + r0 + threadIdx.x] = h;
        Tl[(size_t)(c0 + r) * R + r0 + threadIdx.x] = __float2half_rn(v - __half2float(h));
    }
}

// ---------------- V transpose: V[b][n][d] fp32 -> Vt[b][d][n] fp16 (hi only) ----------------
__global__ void vtrans_kernel(const float* __restrict__ V, __half* __restrict__ Th)
{
    __shared__ float t[32][33];
    const int b = blockIdx.z;
    const float* Vb = V + (size_t)b * SEQ * DIM;
    const int n0 = blockIdx.x * 32, d0 = blockIdx.y * 32;
    #pragma unroll
    for (int r = threadIdx.y; r < 32; r += 8)
        t[r][threadIdx.x] = Vb[(size_t)(n0 + r) * DIM + d0 + threadIdx.x];
    __syncthreads();
    __half* Thb = Th + (size_t)b * DIM * SEQ;
    #pragma unroll
    for (int r = threadIdx.y; r < 32; r += 8)
        Thb[(size_t)(d0 + r) * SEQ + n0 + threadIdx.x] = __float2half_rn(t[threadIdx.x][r]);
}

// ---------------- softmax over QUERY axis (n of S[b][n][m]); writes fp16 alpha ----------------
__global__ void softmax_cols_kernel(const float* __restrict__ S, __half* __restrict__ Ah)
{
    const int b = blockIdx.y;
    const int m = blockIdx.x * blockDim.x + threadIdx.x;
    const float* Sb = S + (size_t)b * SEQ * SEQ;
    __half* Ahb = Ah + (size_t)b * SEQ * SEQ;

    float mx = -3.4e38f, s = 0.f;
    for (int n = 0; n < SEQ; ++n) {
        const float x = Sb[(size_t)n * SEQ + m];
        const float nm = fmaxf(mx, x);
        s = s * __expf(mx - nm) + __expf(x - nm);
        mx = nm;
    }
    const float inv = 1.f / s;
    for (int n = 0; n < SEQ; ++n) {
        const float x = Sb[(size_t)n * SEQ + m];
        Ahb[(size_t)n * SEQ + m] = __float2half_rn(__expf(x - mx) * inv);
    }
}

// ---------------- launch ----------------
extern "C" void kernel_launch(void* const* d_in, const int* in_sizes, int n_in,
                              void* d_out, int out_size)
{
    const float* img  = (const float*)d_in[0];
    const float* text = (const float*)d_in[1];
    const float* Wq   = (const float*)d_in[2];
    const float* Wk   = (const float*)d_in[3];
    const float* Wv   = (const float*)d_in[4];

    float* out  = (float*)d_out;
    float* feat = out + (size_t)MT * DIM;

    __half *imgh, *imgl, *texth, *textl, *wqth, *wqtl, *wkth, *wktl, *wvh;
    __half *gth, *gtl, *uh, *ul, *vth, *ah;
    float *v, *s, *p;
    cudaGetSymbolAddress((void**)&imgh, g_img_h);   cudaGetSymbolAddress((void**)&imgl, g_img_l);
    cudaGetSymbolAddress((void**)&texth, g_text_h); cudaGetSymbolAddress((void**)&textl, g_text_l);
    cudaGetSymbolAddress((void**)&wqth, g_Wqt_h);   cudaGetSymbolAddress((void**)&wqtl, g_Wqt_l);
    cudaGetSymbolAddress((void**)&wkth, g_Wkt_h);   cudaGetSymbolAddress((void**)&wktl, g_Wkt_l);
    cudaGetSymbolAddress((void**)&wvh, g_Wv_h);
    cudaGetSymbolAddress((void**)&gth, g_Gt_h);     cudaGetSymbolAddress((void**)&gtl, g_Gt_l);
    cudaGetSymbolAddress((void**)&p, g_P);
    cudaGetSymbolAddress((void**)&uh, g_U_h);       cudaGetSymbolAddress((void**)&ul, g_U_l);
    cudaGetSymbolAddress((void**)&v, g_V);
    cudaGetSymbolAddress((void**)&vth, g_Vth);
    cudaGetSymbolAddress((void**)&s, g_S);
    cudaGetSymbolAddress((void**)&ah, g_Ah);

    // smem sizes per instantiation (3 stages)
    constexpr int SM_GT = 3 * (2 * TILEB_A + 2 * TILEB_A);      // 122880  <2,2,0,1,1>
    constexpr int SM_U  = 3 * (2 * TILEB_A + 2 * TILEB_A);      // 122880  <2,2,1,1,0>
    constexpr int SM_VP = 3 * (1 * TILEB_A + 1 * TILEB_A);      // 61440   <1,1,0,1,0>
    constexpr int SM_S  = 3 * (2 * TILEB_A + 2 * 2 * TILEB_A);  // 184320  <2,2,0,2,0>
    constexpr int SM_AV = 3 * (1 * TILEB_A + 1 * TILEB_A);      // 61440   <1,1,2,1,0>
    cudaFuncSetAttribute(gemm_h<2,2,0,1,1>, cudaFuncAttributeMaxDynamicSharedMemorySize, SM_GT);
    cudaFuncSetAttribute(gemm_h<2,2,1,1,0>, cudaFuncAttributeMaxDynamicSharedMemorySize, SM_U);
    cudaFuncSetAttribute(gemm_h<1,1,0,1,0>, cudaFuncAttributeMaxDynamicSharedMemorySize, SM_VP);
    cudaFuncSetAttribute(gemm_h<2,2,0,2,0>, cudaFuncAttributeMaxDynamicSharedMemorySize, SM_S);
    cudaFuncSetAttribute(gemm_h<1,1,2,1,0>, cudaFuncAttributeMaxDynamicSharedMemorySize, SM_AV);

    const long nd = (long)SEQ * DIM;    // 2 M
    const long nn = (long)SEQ * SEQ;    // 4 M
    dim3 blk(256);

    // 1. split img/text; split Wv (hi only); transpose-split Wq, Wk
    {
        const int n4i = MT * DIM / 4;
        split_kernel<<<n4i / 256, 256>>>(img,  imgh,  imgl,  n4i);
        split_kernel<<<n4i / 256, 256>>>(text, texth, textl, n4i);
        const int n4w = DIM * DIM / 4;
        split_kernel<<<n4w / 256, 256>>>(Wv, wvh, nullptr, n4w);
        dim3 gt(DIM / 32, DIM / 32), bt(32, 8);
        tsplit_kernel<<<gt, bt>>>(Wq, wqth, wqtl, DIM, DIM);  // Wqt[d,i]
        tsplit_kernel<<<gt, bt>>>(Wk, wkth, wktl, DIM, DIM);  // Wkt[e,i]
    }

    // 2. Gt[e,d] = sum_i Wkt[e,i] * Wqt[d,i]  — split-K x8 partials, then reduce+split
    {
        dim3 g(DIM / 128, DIM / 128, 8);
        gemm_h<2,2,0,1,1><<<g, blk, SM_GT>>>(wkth, wktl, wqth, wqtl, DIM, DIM, DIM, DIM / 8,
                                             0, 0, (long)DIM * DIM,
                                             p, nullptr, nullptr, nullptr, nullptr, 0);
        const int n4g = DIM * DIM / 4;
        reduce_split_kernel<<<n4g / 256, 256>>>(p, gth, gtl, n4g);
    }

    // 3. U[n,e] = sum_d img[n,d] * Gt[e,d]   (3-term, split fp16 out)
    //    V[n,i] = sum_e text[n,e] * Wv[i,e]  (1-term: text hi x Wv hi)
    {
        dim3 g(DIM / 128, MT / 128, 1);
        gemm_h<2,2,1,1,0><<<g, blk, SM_U>>>(imgh, imgl, gth, gtl, MT, DIM, DIM, DIM, 0, 0, 0,
                                            nullptr, uh, ul, nullptr, nullptr, 0);
        gemm_h<1,1,0,1,0><<<g, blk, SM_VP>>>(texth, nullptr, wvh, nullptr, MT, DIM, DIM, DIM, 0, 0, 0,
                                             v, nullptr, nullptr, nullptr, nullptr, 0);
    }

    // 4. transpose V (hi limb only)
    {
        dim3 g(SEQ / 32, DIM / 32, BB), bt(32, 8);
        vtrans_kernel<<<g, bt>>>(v, vth);
    }

    // 5. scores: per batch S[n,m] = sum_e U[n,e] * text[m,e]   (3-term, BN=256)
    {
        dim3 g(SEQ / 256, SEQ / 128, BB);
        gemm_h<2,2,0,2,0><<<g, blk, SM_S>>>(uh, ul, texth, textl, SEQ, SEQ, DIM, DIM, nd, nd, nn,
                                            s, nullptr, nullptr, nullptr, nullptr, 0);
    }

    // 6. softmax over query axis -> fp16 alpha
    {
        dim3 g(SEQ / 256, BB);
        softmax_cols_kernel<<<g, blk>>>(s, ah);
    }

    // 7. out = alpha_h @ Vt_h (1 term, BN=128); feature = out + text
    {
        dim3 g(DIM / 128, SEQ / 128, BB);
        gemm_h<1,1,2,1,0><<<g, blk, SM_AV>>>(ah, nullptr, vth, nullptr, SEQ, DIM, SEQ, SEQ, nn, nd, nd,
                                             out, nullptr, nullptr, text, feat, nd);
    }
}

// round 17
// speedup vs baseline: 3.7878x; 1.0682x over previous
#include <cuda_runtime.h>
#include <cuda_fp16.h>
#include <cstdint>

// ---------------- problem constants ----------------
#define BB   8
#define SEQ  2048
#define DIM  1024
#define MT   (BB * SEQ)          // 16384 flattened rows

// ---------------- PTX helpers (base-target legal, sm_80+) ----------------
__device__ __forceinline__ uint32_t smem_to_u32(const void* p) {
    uint32_t a;
    asm("{ .reg .u64 t; cvta.to.shared.u64 t, %1; cvt.u32.u64 %0, t; }" : "=r"(a) : "l"(p));
    return a;
}
#define CP_ASYNC16(dst, src) \
    asm volatile("cp.async.cg.shared.global [%0], [%1], 16;" :: "r"(dst), "l"(src))
#define CP_COMMIT() asm volatile("cp.async.commit_group;" ::: "memory")
#define CP_WAIT2()  asm volatile("cp.async.wait_group 2;" ::: "memory")
#define CP_WAIT1()  asm volatile("cp.async.wait_group 1;" ::: "memory")
#define CP_WAIT0()  asm volatile("cp.async.wait_group 0;" ::: "memory")

__device__ __forceinline__ void ldsm_x4(uint32_t* r, uint32_t addr) {
    asm volatile("ldmatrix.sync.aligned.m8n8.x4.shared.b16 {%0,%1,%2,%3}, [%4];"
                 : "=r"(r[0]), "=r"(r[1]), "=r"(r[2]), "=r"(r[3]) : "r"(addr));
}
__device__ __forceinline__ void mma16816(float* c, const uint32_t* a, const uint32_t* b) {
    asm volatile(
        "mma.sync.aligned.m16n8k16.row.col.f32.f16.f16.f32 "
        "{%0,%1,%2,%3}, {%4,%5,%6,%7}, {%8,%9}, {%0,%1,%2,%3};"
        : "+f"(c[0]), "+f"(c[1]), "+f"(c[2]), "+f"(c[3])
        : "r"(a[0]), "r"(a[1]), "r"(a[2]), "r"(a[3]), "r"(b[0]), "r"(b[1]));
}

// ---------------- scratch (no cudaMalloc allowed) ----------------
__device__ __half g_img_h[(size_t)MT * DIM], g_img_l[(size_t)MT * DIM];
__device__ __half g_text_h[(size_t)MT * DIM], g_text_l[(size_t)MT * DIM];
__device__ __half g_Wqt_h[(size_t)DIM * DIM], g_Wqt_l[(size_t)DIM * DIM];   // Wq^T [d,i]
__device__ __half g_Wkt_h[(size_t)DIM * DIM], g_Wkt_l[(size_t)DIM * DIM];   // Wk^T [e,i]
__device__ __half g_Wv_h[(size_t)DIM * DIM];
__device__ __half g_Gt_h[(size_t)DIM * DIM], g_Gt_l[(size_t)DIM * DIM];     // G^T [e,d]
__device__ float  g_P[(size_t)8 * DIM * DIM];                                // split-K partials
__device__ __half g_U_h[(size_t)MT * DIM], g_U_l[(size_t)MT * DIM];         // img @ G
__device__ __half g_Vth[(size_t)MT * DIM];                                   // [B][DIM][SEQ]
__device__ float  g_S[(size_t)BB * SEQ * SEQ];
__device__ __half g_Ah[(size_t)BB * SEQ * SEQ];

// ---------------- GEMM: C[M,Nc] ~= (A0[+A1]) @ (B0[+B1])^T, fp16 HMMA ----------------
// Terms: A0B0 always; A0B1 if TB==2; A1B0 if TA==2 (A1B1 dropped).
// BM=128, BN=128*NH, BK=32, 3-stage cp.async, warp tile 64 x 32*NH (8 warps 2x4).
// SMEM rows 80B (64B data + 16 pad) -> conflict-free ldmatrix & cp.async.
// SK=1: blockIdx.z = K-chunk (offset z*Klen into K of A and B; C += z*sC as partial).
// EPI 0: fp32 C   1: split fp16 Ch/Cl   2: fp32 C + feat=C+text
// EPI 3: fp16 TRANSPOSED write via smem staging: Ch = Vt[b][d][n], b from mBase (NH==1 only)
#define ROWB     80
#define TILEB_A  (128 * ROWB)            // 10240
#define TPC      136                      // transpose staging row stride (halves)

template<int TA, int TB, int EPI, int NH, int SK, int MINB>
__global__ void __launch_bounds__(256, MINB)
gemm_h(const __half* __restrict__ A0, const __half* __restrict__ A1,
       const __half* __restrict__ B0, const __half* __restrict__ B1,
       int M, int Nc, int Kd, int Klen, long sA, long sB, long sC,
       float* __restrict__ C, __half* __restrict__ Ch, __half* __restrict__ Cl,
       const float* __restrict__ text, float* __restrict__ feat, long sT)
{
    constexpr uint32_t TILEB_B = (uint32_t)(128 * NH * ROWB);
    constexpr uint32_t T_A0 = 0;
    constexpr uint32_t T_A1 = TILEB_A;                 // valid iff TA==2
    constexpr uint32_t T_B0 = TA * TILEB_A;
    constexpr uint32_t T_B1 = T_B0 + TILEB_B;          // valid iff TB==2
    constexpr uint32_t STAGE_SZ = TA * TILEB_A + TB * TILEB_B;

    extern __shared__ char smem[];
    const uint32_t sbase = smem_to_u32(smem);
    const int tid = threadIdx.x;
    const int wid = tid >> 5;
    const int lid = tid & 31;
    const int b = blockIdx.z;

    const int mBase = blockIdx.y * 128;
    const int nBase = blockIdx.x * (128 * NH);

    const long aoff = SK ? (long)b * Klen : (long)b * sA;
    const long boff = SK ? (long)b * Klen : (long)b * sB;
    const __half* gA0 = A0 + aoff + (long)mBase * Kd;
    const __half* gA1 = (TA == 2) ? A1 + aoff + (long)mBase * Kd : nullptr;
    const __half* gB0 = B0 + boff + (long)nBase * Kd;
    const __half* gB1 = (TB == 2) ? B1 + boff + (long)nBase * Kd : nullptr;

    auto load_stage = [&](int k0, int s) {
        const uint32_t st = sbase + (uint32_t)s * STAGE_SZ;
        #pragma unroll
        for (int c = 0; c < 2; ++c) {          // A: 512 16B chunks per tile
            const int ch = tid + c * 256;
            const int r = ch >> 2, col = (ch & 3) * 16;
            CP_ASYNC16(st + T_A0 + r * ROWB + col, (const char*)(gA0 + (long)r * Kd + k0) + col);
            if (TA == 2)
                CP_ASYNC16(st + T_A1 + r * ROWB + col, (const char*)(gA1 + (long)r * Kd + k0) + col);
        }
        #pragma unroll
        for (int c = 0; c < 2 * NH; ++c) {     // B: 512*NH chunks per tile
            const int ch = tid + c * 256;
            const int r = ch >> 2, col = (ch & 3) * 16;
            CP_ASYNC16(st + T_B0 + r * ROWB + col, (const char*)(gB0 + (long)r * Kd + k0) + col);
            if (TB == 2)
                CP_ASYNC16(st + T_B1 + r * ROWB + col, (const char*)(gB1 + (long)r * Kd + k0) + col);
        }
    };

    const int wm = (wid >> 2) * 64;
    const int wn = (wid & 3) * (32 * NH);

    const uint32_t aOff = (uint32_t)((lid & 15) * ROWB + (lid >> 4) * 16);
    const uint32_t bOff = (uint32_t)((((lid >> 4) << 3) + (lid & 7)) * ROWB + ((lid >> 3) & 1) * 16);

    float acc[4][4 * NH][4];
    #pragma unroll
    for (int mi = 0; mi < 4; ++mi)
        #pragma unroll
        for (int ni = 0; ni < 4 * NH; ++ni)
            #pragma unroll
            for (int q = 0; q < 4; ++q) acc[mi][ni][q] = 0.f;

    const int nch = Klen >> 5;

    load_stage(0, 0);  CP_COMMIT();
    load_stage(32, 1); CP_COMMIT();

    int cur = 0, nxt = 2;
    for (int i = 0; i < nch; ++i) {
        if (i + 2 < nch)      { load_stage((i + 2) << 5, nxt); CP_COMMIT(); CP_WAIT2(); }
        else if (i + 1 < nch) { CP_WAIT1(); }
        else                  { CP_WAIT0(); }
        __syncthreads();

        const uint32_t st = sbase + (uint32_t)cur * STAGE_SZ;
        const uint32_t aBase = st + (uint32_t)(wm * ROWB);
        const uint32_t bBase = st + (uint32_t)(wn * ROWB);

        #pragma unroll
        for (int kk = 0; kk < 2; ++kk) {
            const uint32_t kb = kk * 32;
            uint32_t a0r[4][4], a1r[4][4];
            #pragma unroll
            for (int mi = 0; mi < 4; ++mi) {
                ldsm_x4(a0r[mi], aBase + T_A0 + (uint32_t)(mi * 16 * ROWB) + aOff + kb);
                if (TA == 2)
                    ldsm_x4(a1r[mi], aBase + T_A1 + (uint32_t)(mi * 16 * ROWB) + aOff + kb);
            }
            #pragma unroll
            for (int nh = 0; nh < NH; ++nh) {
                uint32_t b0r[8], b1r[8];
                #pragma unroll
                for (int nb = 0; nb < 2; ++nb) {
                    const uint32_t nrow = (uint32_t)((nh * 32 + nb * 16) * ROWB);
                    ldsm_x4(&b0r[nb * 4], bBase + T_B0 + nrow + bOff + kb);
                    if (TB == 2)
                        ldsm_x4(&b1r[nb * 4], bBase + T_B1 + nrow + bOff + kb);
                }
                #pragma unroll
                for (int mi = 0; mi < 4; ++mi)
                    #pragma unroll
                    for (int nj = 0; nj < 4; ++nj) {
                        float* a4 = acc[mi][nh * 4 + nj];
                        mma16816(a4, a0r[mi], &b0r[nj * 2]);
                        if (TB == 2) mma16816(a4, a0r[mi], &b1r[nj * 2]);
                        if (TA == 2) mma16816(a4, a1r[mi], &b0r[nj * 2]);
                    }
            }
        }
        __syncthreads();
        cur = (cur == 2) ? 0 : cur + 1;
        nxt = (nxt == 2) ? 0 : nxt + 1;
    }

    // ---- epilogue ----
    if (EPI == 3) {
        // transpose tile through smem, then coalesced fp16 write to Vt[b][d][n]
        __half* tp = (__half*)smem;
        const int rowL = wm + (lid >> 2);
        const int colL = wn + (lid & 3) * 2;
        #pragma unroll
        for (int mi = 0; mi < 4; ++mi)
            #pragma unroll
            for (int half = 0; half < 2; ++half) {
                const int row = rowL + mi * 16 + half * 8;
                #pragma unroll
                for (int ni = 0; ni < 4 * NH; ++ni) {
                    const int col = colL + ni * 8;
                    tp[(col + 0) * TPC + row] = __float2half_rn(acc[mi][ni][half * 2 + 0]);
                    tp[(col + 1) * TPC + row] = __float2half_rn(acc[mi][ni][half * 2 + 1]);
                }
            }
        __syncthreads();
        const int bb = mBase >> 11;            // batch (SEQ=2048 rows per batch)
        const int n0wb = mBase & (SEQ - 1);    // n offset within batch
        #pragma unroll
        for (int u = tid; u < 1024; u += 256) {
            const int d = u >> 3;              // local d row 0..127
            const int c = (u & 7) * 16;        // half offset 0..112
            const uint4 v = *(const uint4*)(tp + d * TPC + c);
            *(uint4*)(Ch + ((size_t)bb * DIM + nBase + d) * SEQ + n0wb + c) = v;
            const uint4 v2 = *(const uint4*)(tp + d * TPC + c + 8);
            *(uint4*)(Ch + ((size_t)bb * DIM + nBase + d) * SEQ + n0wb + c + 8) = v2;
        }
        return;
    }

    const int rowA = mBase + wm + (lid >> 2);
    const int colA = nBase + wn + (lid & 3) * 2;
    #pragma unroll
    for (int mi = 0; mi < 4; ++mi) {
        #pragma unroll
        for (int half = 0; half < 2; ++half) {
            const int row = rowA + mi * 16 + half * 8;
            #pragma unroll
            for (int ni = 0; ni < 4 * NH; ++ni) {
                const int col = colA + ni * 8;
                const float v0 = acc[mi][ni][half * 2 + 0];
                const float v1 = acc[mi][ni][half * 2 + 1];
                if (EPI == 0) {
                    float2 v; v.x = v0; v.y = v1;
                    *(float2*)(C + (long)b * sC + (long)row * Nc + col) = v;
                } else if (EPI == 1) {
                    const __half h0 = __float2half_rn(v0);
                    const __half h1 = __float2half_rn(v1);
                    __half2 ph, pl;
                    ph.x = h0; ph.y = h1;
                    pl.x = __float2half_rn(v0 - __half2float(h0));
                    pl.y = __float2half_rn(v1 - __half2float(h1));
                    *(__half2*)(Ch + (long)b * sC + (long)row * Nc + col) = ph;
                    *(__half2*)(Cl + (long)b * sC + (long)row * Nc + col) = pl;
                } else {
                    float2 v; v.x = v0; v.y = v1;
                    *(float2*)(C + (long)b * sC + (long)row * Nc + col) = v;
                    const float2 t = *(const float2*)(text + (long)b * sT + (long)row * Nc + col);
                    float2 f; f.x = v.x + t.x; f.y = v.y + t.y;
                    *(float2*)(feat + (long)b * sT + (long)row * Nc + col) = f;
                }
            }
        }
    }
}

// ---------------- split-K reduce + fp16 hi/lo split ----------------
__global__ void reduce_split_kernel(const float* __restrict__ P,
                                    __half* __restrict__ h, __half* __restrict__ l, int n4)
{
    const int i = blockIdx.x * blockDim.x + threadIdx.x;
    if (i >= n4) return;
    float4 s = ((const float4*)P)[i];
    #pragma unroll
    for (int p = 1; p < 8; ++p) {
        const float4 v = ((const float4*)P)[(size_t)p * (DIM * (size_t)DIM / 4) + i];
        s.x += v.x; s.y += v.y; s.z += v.z; s.w += v.w;
    }
    union { uint2 u; __half q[4]; } ph, pl;
    #pragma unroll
    for (int q = 0; q < 4; ++q) {
        const float x = (&s.x)[q];
        const __half hh = __float2half_rn(x);
        ph.q[q] = hh;
        pl.q[q] = __float2half_rn(x - __half2float(hh));
    }
    ((uint2*)h)[i] = ph.u;
    ((uint2*)l)[i] = pl.u;
}

// ---------------- fp32 -> fp16 hi/lo split ----------------
__global__ void split_kernel(const float* __restrict__ s, __half* __restrict__ h,
                             __half* __restrict__ l, int n4)
{
    const int i = blockIdx.x * blockDim.x + threadIdx.x;
    if (i >= n4) return;
    const float4 v = ((const float4*)s)[i];
    union { uint2 u; __half q[4]; } ph, pl;
    #pragma unroll
    for (int q = 0; q < 4; ++q) {
        const float x = (&v.x)[q];
        const __half hh = __float2half_rn(x);
        ph.q[q] = hh;
        if (l) pl.q[q] = __float2half_rn(x - __half2float(hh));
    }
    ((uint2*)h)[i] = ph.u;
    if (l) ((uint2*)l)[i] = pl.u;
}

// ---------------- transpose + split: A[R,C] fp32 -> Th/Tl[C,R] fp16 ----------------
__global__ void tsplit_kernel(const float* __restrict__ A,
                              __half* __restrict__ Th, __half* __restrict__ Tl, int R, int C)
{
    __shared__ float t[32][33];
    const int r0 = blockIdx.x * 32, c0 = blockIdx.y * 32;
    #pragma unroll
    for (int r = threadIdx.y; r < 32; r += 8)
        t[r][threadIdx.x] = A[(size_t)(r0 + r) * C + c0 + threadIdx.x];
    __syncthreads();
    #pragma unroll
    for (int r = threadIdx.y; r < 32; r += 8) {
        const float v = t[threadIdx.x][r];
        const __half h = __float2half_rn(v);
        Th[(size_t)(c0 + r) * R + r0 + threadIdx.x] = h;
        Tl[(size_t)(c0 + r) * R + r0 + threadIdx.x] = __float2half_rn(v - __half2float(h));
    }
}

// ---------------- softmax over QUERY axis (n of S[b][n][m]); writes fp16 alpha ----------------
__global__ void softmax_cols_kernel(const float* __restrict__ S, __half* __restrict__ Ah)
{
    const int b = blockIdx.y;
    const int m = blockIdx.x * blockDim.x + threadIdx.x;
    const float* Sb = S + (size_t)b * SEQ * SEQ;
    __half* Ahb = Ah + (size_t)b * SEQ * SEQ;

    float mx = -3.4e38f, s = 0.f;
    for (int n = 0; n < SEQ; ++n) {
        const float x = Sb[(size_t)n * SEQ + m];
        const float nm = fmaxf(mx, x);
        s = s * __expf(mx - nm) + __expf(x - nm);
        mx = nm;
    }
    const float inv = 1.f / s;
    for (int n = 0; n < SEQ; ++n) {
        const float x = Sb[(size_t)n * SEQ + m];
        Ahb[(size_t)n * SEQ + m] = __float2half_rn(__expf(x - mx) * inv);
    }
}

// ---------------- launch ----------------
extern "C" void kernel_launch(void* const* d_in, const int* in_sizes, int n_in,
                              void* d_out, int out_size)
{
    const float* img  = (const float*)d_in[0];
    const float* text = (const float*)d_in[1];
    const float* Wq   = (const float*)d_in[2];
    const float* Wk   = (const float*)d_in[3];
    const float* Wv   = (const float*)d_in[4];

    float* out  = (float*)d_out;
    float* feat = out + (size_t)MT * DIM;

    __half *imgh, *imgl, *texth, *textl, *wqth, *wqtl, *wkth, *wktl, *wvh;
    __half *gth, *gtl, *uh, *ul, *vth, *ah;
    float *s, *p;
    cudaGetSymbolAddress((void**)&imgh, g_img_h);   cudaGetSymbolAddress((void**)&imgl, g_img_l);
    cudaGetSymbolAddress((void**)&texth, g_text_h); cudaGetSymbolAddress((void**)&textl, g_text_l);
    cudaGetSymbolAddress((void**)&wqth, g_Wqt_h);   cudaGetSymbolAddress((void**)&wqtl, g_Wqt_l);
    cudaGetSymbolAddress((void**)&wkth, g_Wkt_h);   cudaGetSymbolAddress((void**)&wktl, g_Wkt_l);
    cudaGetSymbolAddress((void**)&wvh, g_Wv_h);
    cudaGetSymbolAddress((void**)&gth, g_Gt_h);     cudaGetSymbolAddress((void**)&gtl, g_Gt_l);
    cudaGetSymbolAddress((void**)&p, g_P);
    cudaGetSymbolAddress((void**)&uh, g_U_h);       cudaGetSymbolAddress((void**)&ul, g_U_l);
    cudaGetSymbolAddress((void**)&vth, g_Vth);
    cudaGetSymbolAddress((void**)&s, g_S);
    cudaGetSymbolAddress((void**)&ah, g_Ah);

    // smem sizes per instantiation (3 stages)
    constexpr int SM_GT = 3 * (2 * TILEB_A + 2 * TILEB_A);      // 122880
    constexpr int SM_U  = 3 * (2 * TILEB_A + 2 * TILEB_A);      // 122880
    constexpr int SM_VP = 3 * (1 * TILEB_A + 1 * TILEB_A);      // 61440
    constexpr int SM_S  = 3 * (2 * TILEB_A + 2 * 2 * TILEB_A);  // 184320
    constexpr int SM_AV = 3 * (1 * TILEB_A + 1 * TILEB_A);      // 61440
    cudaFuncSetAttribute(gemm_h<2,2,0,1,1,1>, cudaFuncAttributeMaxDynamicSharedMemorySize, SM_GT);
    cudaFuncSetAttribute(gemm_h<2,2,1,1,0,1>, cudaFuncAttributeMaxDynamicSharedMemorySize, SM_U);
    cudaFuncSetAttribute(gemm_h<1,1,3,1,0,2>, cudaFuncAttributeMaxDynamicSharedMemorySize, SM_VP);
    cudaFuncSetAttribute(gemm_h<2,2,0,2,0,1>, cudaFuncAttributeMaxDynamicSharedMemorySize, SM_S);
    cudaFuncSetAttribute(gemm_h<1,1,2,1,0,2>, cudaFuncAttributeMaxDynamicSharedMemorySize, SM_AV);

    const long nd = (long)SEQ * DIM;    // 2 M
    const long nn = (long)SEQ * SEQ;    // 4 M
    dim3 blk(256);

    // 1. split img/text; split Wv (hi only); transpose-split Wq, Wk
    {
        const int n4i = MT * DIM / 4;
        split_kernel<<<n4i / 256, 256>>>(img,  imgh,  imgl,  n4i);
        split_kernel<<<n4i / 256, 256>>>(text, texth, textl, n4i);
        const int n4w = DIM * DIM / 4;
        split_kernel<<<n4w / 256, 256>>>(Wv, wvh, nullptr, n4w);
        dim3 gt(DIM / 32, DIM / 32), bt(32, 8);
        tsplit_kernel<<<gt, bt>>>(Wq, wqth, wqtl, DIM, DIM);  // Wqt[d,i]
        tsplit_kernel<<<gt, bt>>>(Wk, wkth, wktl, DIM, DIM);  // Wkt[e,i]
    }

    // 2. Gt[e,d] = sum_i Wkt[e,i] * Wqt[d,i]  — split-K x8 partials, then reduce+split
    {
        dim3 g(DIM / 128, DIM / 128, 8);
        gemm_h<2,2,0,1,1,1><<<g, blk, SM_GT>>>(wkth, wktl, wqth, wqtl, DIM, DIM, DIM, DIM / 8,
                                               0, 0, (long)DIM * DIM,
                                               p, nullptr, nullptr, nullptr, nullptr, 0);
        const int n4g = DIM * DIM / 4;
        reduce_split_kernel<<<n4g / 256, 256>>>(p, gth, gtl, n4g);
    }

    // 3. U[n,e] = sum_d img[n,d] * Gt[e,d]   (3-term, split fp16 out)
    //    Vt[b][d][n] = (text_h @ Wv_h^T)^T   (1-term, fused transpose epilogue)
    {
        dim3 g(DIM / 128, MT / 128, 1);
        gemm_h<2,2,1,1,0,1><<<g, blk, SM_U>>>(imgh, imgl, gth, gtl, MT, DIM, DIM, DIM, 0, 0, 0,
                                              nullptr, uh, ul, nullptr, nullptr, 0);
        gemm_h<1,1,3,1,0,2><<<g, blk, SM_VP>>>(texth, nullptr, wvh, nullptr, MT, DIM, DIM, DIM, 0, 0, 0,
                                               nullptr, vth, nullptr, nullptr, nullptr, 0);
    }

    // 4. scores: per batch S[n,m] = sum_e U[n,e] * text[m,e]   (3-term, BN=256)
    {
        dim3 g(SEQ / 256, SEQ / 128, BB);
        gemm_h<2,2,0,2,0,1><<<g, blk, SM_S>>>(uh, ul, texth, textl, SEQ, SEQ, DIM, DIM, nd, nd, nn,
                                              s, nullptr, nullptr, nullptr, nullptr, 0);
    }

    // 5. softmax over query axis -> fp16 alpha
    {
        dim3 g(SEQ / 256, BB);
        softmax_cols_kernel<<<g, blk>>>(s, ah);
    }

    // 6. out = alpha_h @ Vt_h (1 term, BN=128); feature = out + text
    {
        dim3 g(DIM / 128, SEQ / 128, BB);
        gemm_h<1,1,2,1,0,2><<<g, blk, SM_AV>>>(ah, nullptr, vth, nullptr, SEQ, DIM, SEQ, SEQ, nn, nd, nd,
                                               out, nullptr, nullptr, text, feat, nd);
    }
}